// round 9
// baseline (speedup 1.0000x reference)
#include <cuda_runtime.h>
#include <cstdint>

// Problem dims
#define Bsz   64
#define Lseq  1024
#define Pdim  64
#define Hdim  256
#define OUTD  128

// 16 clusters x 8 CTAs. Cluster: 4 batch rows. CTA: 32 hidden units (96 gate rows).
// 768 threads: thread = (row 0..95, half 0..1, batch 0..3); each computes a half-dot,
// halves combined via shfl_xor(4).
#define CLUSTER  8
#define B_TILE   4
#define NTHREADS 768
#define ROWS     96
#define UNITS    32
// padded layouts: halves offset by +4 words so hf0/hf1 lanes hit different banks
#define WH_PAD   264          // 128 | pad4 | 128 | pad4
#define WH_HALF  132
#define WX_PAD   72           // 32 | pad4 | 32 | pad4
#define WX_HALF  36
#define HB_PAD   264
#define PARTS    12           // final-GEMM K-split (768/64)

struct __align__(16) Smem {
    float Wx[ROWS * WX_PAD];        // encoder W_ih slice (96x64, padded halves)
    float Wh[ROWS * WH_PAD];        // W_hh slice (96x256, padded); reused for decoder
    float hb[2][B_TILE][HB_PAD];    // double-buffered hidden state (padded at 128)
    float xb[B_TILE][WX_PAD];       // staged x_t (padded at 32)
    float Asm[ROWS * B_TILE];       // input-gate partials
    float Gsm[ROWS * B_TILE];       // hidden-gate partials
    float giD[ROWS * B_TILE];       // decoder constant input gates
    float wa[Hdim];                 // attention hidden weight row
    float wdec[Hdim];               // decoder output weight
    float bA[ROWS];
    float bG[ROWS];
    float yb[Lseq * B_TILE];        // decoder outputs y[i][b]
    float red[64 * PARTS];          // final GEMM reduction scratch
};

__device__ __forceinline__ uint32_t s2u(const void* p) {
    uint32_t a;
    asm("{ .reg .u64 t; cvta.to.shared.u64 t, %1; cvt.u32.u64 %0, t; }"
        : "=r"(a) : "l"(p));
    return a;
}

__device__ __forceinline__ uint32_t mapa_r(uint32_t la, int r) {
    uint32_t ra;
    asm("mapa.shared::cluster.u32 %0, %1, %2;" : "=r"(ra) : "r"(la), "r"(r));
    return ra;
}

__device__ __forceinline__ void st_clu(uint32_t ra, float v) {
    asm volatile("st.shared::cluster.b32 [%0], %1;"
                 :: "r"(ra), "r"(__float_as_uint(v)) : "memory");
}

__device__ __forceinline__ void csync() {
    asm volatile("barrier.cluster.arrive.aligned;" ::: "memory");
    asm volatile("barrier.cluster.wait.aligned;" ::: "memory");
}

__device__ __forceinline__ float sigf(float v) { return 1.0f / (1.0f + expf(-v)); }

// Half-dot over NF4 float4 chunks (NF4*4 floats), 4 independent accumulator chains.
// W and v must be 16B-aligned SMEM pointers.
template<int NF4>
__device__ __forceinline__ float doth(const float* __restrict__ W,
                                      const float* __restrict__ v) {
    const float4* w4 = (const float4*)W;
    const float4* v4 = (const float4*)v;
    float a0 = 0.f, a1 = 0.f, a2 = 0.f, a3 = 0.f;
#pragma unroll
    for (int k = 0; k < NF4; k += 2) {
        float4 w = w4[k],     xx = v4[k];
        a0 = fmaf(w.x, xx.x, a0); a1 = fmaf(w.y, xx.y, a1);
        a2 = fmaf(w.z, xx.z, a2); a3 = fmaf(w.w, xx.w, a3);
        float4 w2 = w4[k + 1], x2 = v4[k + 1];
        a0 = fmaf(w2.x, x2.x, a0); a1 = fmaf(w2.y, x2.y, a1);
        a2 = fmaf(w2.z, x2.z, a2); a3 = fmaf(w2.w, x2.w, a3);
    }
    return (a0 + a1) + (a2 + a3);
}

__global__ void __cluster_dims__(CLUSTER, 1, 1) __launch_bounds__(NTHREADS, 1)
attn_net_kernel(const float* __restrict__ x,
                const float* __restrict__ Wihe, const float* __restrict__ Whhe,
                const float* __restrict__ bihe, const float* __restrict__ bhhe,
                const float* __restrict__ Wihd, const float* __restrict__ Whhd,
                const float* __restrict__ bihd, const float* __restrict__ bhhd,
                const float* __restrict__ Wdec, const float* __restrict__ bdec_p,
                const float* __restrict__ Wattn, const float* __restrict__ battn,
                const float* __restrict__ Wout, const float* __restrict__ bout,
                float* __restrict__ out)
{
    extern __shared__ char smem_raw[];
    Smem& S = *reinterpret_cast<Smem*>(smem_raw);

    const int tid = threadIdx.x;
    uint32_t rank;
    asm("mov.u32 %0, %%cluster_ctarank;" : "=r"(rank));
    const int g   = blockIdx.x >> 3;        // cluster id 0..15
    const int b0  = g * B_TILE;             // batch base
    const int U0  = (int)rank * UNITS;      // hidden-unit base for this CTA
    const int PADU = U0 + ((int)rank >= 4 ? 4 : 0);  // padded index into hb rows
    const int row = tid >> 3;               // 0..95
    const int hf  = (tid >> 2) & 1;         // half 0/1
    const int bb  = tid & 3;                // batch 0..3

    // ---------------- Phase 0: load weight slices (padded layouts) ----------------
    for (int idx = tid; idx < ROWS * Pdim; idx += NTHREADS) {
        int lr = idx >> 6, k = idx & 63;
        int grow = (lr >> 5) * Hdim + U0 + (lr & 31);
        S.Wx[lr * WX_PAD + k + (k >= 32 ? 4 : 0)] = Wihe[grow * Pdim + k];
    }
    for (int idx = tid; idx < ROWS * Hdim; idx += NTHREADS) {
        int lr = idx >> 8, k = idx & 255;
        int grow = (lr >> 5) * Hdim + U0 + (lr & 31);
        S.Wh[lr * WH_PAD + k + (k >= 128 ? 4 : 0)] = Whhe[grow * Hdim + k];
    }
    for (int idx = tid; idx < ROWS; idx += NTHREADS) {
        int grow = (idx >> 5) * Hdim + U0 + (idx & 31);
        S.bA[idx] = bihe[grow];
        S.bG[idx] = bhhe[grow];
    }
    for (int idx = tid; idx < Hdim; idx += NTHREADS) {
        S.wa[idx]   = Wattn[Hdim + idx];   // W_attn[0, H + idx]
        S.wdec[idx] = Wdec[idx];           // W_dec_out[0, idx]
    }
    for (int idx = tid; idx < 2 * B_TILE * HB_PAD; idx += NTHREADS)
        ((float*)S.hb)[idx] = 0.f;
    __syncthreads();
    csync();

    // Remote DSMEM addresses for the per-step h broadcast (combine threads only):
    uint32_t raddr[2][CLUSTER];
    if (tid < UNITS * B_TILE) {
        int u = tid >> 2, b = tid & 3;
#pragma unroll
        for (int buf = 0; buf < 2; buf++) {
            uint32_t la = s2u(&S.hb[buf][b][PADU + u]);
#pragma unroll
            for (int pr = 0; pr < CLUSTER; pr++)
                raddr[buf][pr] = mapa_r(la, pr);
        }
    }

    // Per-warp (warps 0-3 = batches 0-3) online-softmax state in registers.
    float m_run = -3.0e38f, Z_run = 0.f, C_run = 0.f;

    // ---------------- Phase 1: encoder GRU + online-softmax attention ----------------
    float rx = 0.f;
    if (tid < 256)
        rx = x[(b0 + (tid >> 6)) * (Lseq * Pdim) + (tid & 63)];

    for (int t = 0; t < Lseq; t++) {
        const int cur = t & 1, nxt = cur ^ 1;

        if (tid < 256) {
            int e = tid & 63;
            S.xb[tid >> 6][e + (e >= 32 ? 4 : 0)] = rx;
        }
        __syncthreads();
        if (tid < 256 && (t + 1) < Lseq)
            rx = x[(b0 + (tid >> 6)) * (Lseq * Pdim) + (t + 1) * Pdim + (tid & 63)];

        // half-GEMVs: thread owns (row, half, batch); shfl_xor(4) joins halves
        float ap = doth<8> (&S.Wx[row * WX_PAD + hf * WX_HALF], &S.xb[bb][hf * WX_HALF]);
        float gp = doth<32>(&S.Wh[row * WH_PAD + hf * WH_HALF], &S.hb[cur][bb][hf * WH_HALF]);
        ap += __shfl_xor_sync(0xffffffffu, ap, 4);
        gp += __shfl_xor_sync(0xffffffffu, gp, 4);
        if (hf == 0) {
            S.Asm[row * 4 + bb] = S.bA[row] + ap;
            S.Gsm[row * 4 + bb] = S.bG[row] + gp;
        }
        __syncthreads();

        // combine gates, push new hidden slice to all 8 CTAs
        if (tid < UNITS * B_TILE) {
            int u = tid >> 2, b = tid & 3;
            float r = sigf(S.Asm[u * 4 + b] + S.Gsm[u * 4 + b]);
            float z = sigf(S.Asm[(32 + u) * 4 + b] + S.Gsm[(32 + u) * 4 + b]);
            float n = tanhf(S.Asm[(64 + u) * 4 + b] + r * S.Gsm[(64 + u) * 4 + b]);
            float hn = (1.f - z) * n + z * S.hb[cur][b][PADU + u];
#pragma unroll
            for (int pr = 0; pr < CLUSTER; pr++) st_clu(raddr[nxt][pr], hn);
        }
        csync();

        // warp w owns batch w: h_proj + online softmax + context, in registers
        if (tid < 128) {
            int w = tid >> 5, l = tid & 31;
            float p = 0.f;
#pragma unroll
            for (int j = l; j < 128; j += 32) p += S.hb[nxt][w][j] * S.wa[j];
#pragma unroll
            for (int j = 128 + l; j < 256; j += 32) p += S.hb[nxt][w][j + 4] * S.wa[j];
#pragma unroll
            for (int o = 16; o > 0; o >>= 1) p += __shfl_xor_sync(0xffffffffu, p, o);
            float mn  = fmaxf(m_run, p);
            float sc  = expf(m_run - mn);
            float wgt = expf(p - mn);
            Z_run = Z_run * sc + wgt;
            m_run = mn;
            C_run = C_run * sc + wgt * S.hb[nxt][w][PADU + l];
        }
    }
    // last hidden state s0 lives in hb[0]

    // ---------------- Phase 1.5: context c, decoder constant gates ----------------
    if (tid < 128) {
        int w = tid >> 5, l = tid & 31;
        float cv = C_run / Z_run;
        uint32_t la = s2u(&S.hb[1][w][PADU + l]);
#pragma unroll
        for (int pr = 0; pr < CLUSTER; pr++) st_clu(mapa_r(la, pr), cv);
    }
    csync();

    // decoder input weights -> Wh region; giD = W_ih_d . c + b_ih_d
    for (int idx = tid; idx < ROWS * Hdim; idx += NTHREADS) {
        int lr = idx >> 8, k = idx & 255;
        int grow = (lr >> 5) * Hdim + U0 + (lr & 31);
        S.Wh[lr * WH_PAD + k + (k >= 128 ? 4 : 0)] = Wihd[grow * Hdim + k];
    }
    for (int idx = tid; idx < ROWS; idx += NTHREADS) {
        int grow = (idx >> 5) * Hdim + U0 + (idx & 31);
        S.bA[idx] = bihd[grow];
        S.bG[idx] = bhhd[grow];
    }
    __syncthreads();
    {
        float gp = doth<32>(&S.Wh[row * WH_PAD + hf * WH_HALF], &S.hb[1][bb][hf * WH_HALF]);
        gp += __shfl_xor_sync(0xffffffffu, gp, 4);
        if (hf == 0) S.giD[row * 4 + bb] = S.bA[row] + gp;
    }
    __syncthreads();

    // decoder recurrent weights
    for (int idx = tid; idx < ROWS * Hdim; idx += NTHREADS) {
        int lr = idx >> 8, k = idx & 255;
        int grow = (lr >> 5) * Hdim + U0 + (lr & 31);
        S.Wh[lr * WH_PAD + k + (k >= 128 ? 4 : 0)] = Whhd[grow * Hdim + k];
    }
    const float bdec = bdec_p[0];
    __syncthreads();
    csync();

    // ---------------- Phase 2: decoder GRU (constant input gates) ----------------
    for (int i = 0; i < Lseq; i++) {
        const int cur = i & 1, nxt = cur ^ 1;

        float gp = doth<32>(&S.Wh[row * WH_PAD + hf * WH_HALF], &S.hb[cur][bb][hf * WH_HALF]);
        gp += __shfl_xor_sync(0xffffffffu, gp, 4);
        if (hf == 0) S.Gsm[row * 4 + bb] = S.bG[row] + gp;
        __syncthreads();

        if (tid < 128) {
            int u = tid >> 2, b = tid & 3;
            float r = sigf(S.giD[u * 4 + b] + S.Gsm[u * 4 + b]);
            float z = sigf(S.giD[(32 + u) * 4 + b] + S.Gsm[(32 + u) * 4 + b]);
            float n = tanhf(S.giD[(64 + u) * 4 + b] + r * S.Gsm[(64 + u) * 4 + b]);
            float sn = (1.f - z) * n + z * S.hb[cur][b][PADU + u];
#pragma unroll
            for (int pr = 0; pr < CLUSTER; pr++) st_clu(raddr[nxt][pr], sn);
        }
        csync();

        // y_i[b] = sigmoid(s_new . w_dec + b_dec), warp w = batch w
        if (tid < 128) {
            int w = tid >> 5, l = tid & 31;
            float p = 0.f;
#pragma unroll
            for (int j = l; j < 128; j += 32) p += S.hb[nxt][w][j] * S.wdec[j];
#pragma unroll
            for (int j = 128 + l; j < 256; j += 32) p += S.hb[nxt][w][j + 4] * S.wdec[j];
#pragma unroll
            for (int o = 16; o > 0; o >>= 1) p += __shfl_xor_sync(0xffffffffu, p, o);
            if (l == 0) S.yb[i * 4 + w] = sigf(p + bdec);
        }
    }

    // ---------------- Phase 3: out = y @ W_out^T + b_out ----------------
    __syncthreads();
    {
        int part = tid >> 6;            // 0..11, K-split
        int ob   = tid & 63;            // 16 o-rows x 4 batches
        int o    = (int)rank * 16 + (ob >> 2);
        int b    = ob & 3;
        float acc = 0.f;
        for (int i = part; i < Lseq; i += PARTS)
            acc += S.yb[i * 4 + b] * Wout[o * Lseq + i];
        S.red[ob * PARTS + part] = acc;
    }
    __syncthreads();
    if (tid < 64) {
        int o = (int)rank * 16 + (tid >> 2);
        int b = tid & 3;
        float s = bout[o];
#pragma unroll
        for (int p6 = 0; p6 < PARTS; p6++) s += S.red[tid * PARTS + p6];
        out[(b0 + b) * OUTD + o] = s;
    }
}

extern "C" void kernel_launch(void* const* d_in, const int* in_sizes, int n_in,
                              void* d_out, int out_size) {
    (void)in_sizes; (void)n_in; (void)out_size;
    cudaFuncSetAttribute(attn_net_kernel,
                         cudaFuncAttributeMaxDynamicSharedMemorySize,
                         (int)sizeof(Smem));
    attn_net_kernel<<<128, NTHREADS, sizeof(Smem)>>>(
        (const float*)d_in[0],  (const float*)d_in[1],  (const float*)d_in[2],
        (const float*)d_in[3],  (const float*)d_in[4],  (const float*)d_in[5],
        (const float*)d_in[6],  (const float*)d_in[7],  (const float*)d_in[8],
        (const float*)d_in[9],  (const float*)d_in[10], (const float*)d_in[11],
        (const float*)d_in[12], (const float*)d_in[13], (const float*)d_in[14],
        (float*)d_out);
}

// round 10
// speedup vs baseline: 1.0118x; 1.0118x over previous
#include <cuda_runtime.h>
#include <cstdint>

// Problem dims
#define Bsz   64
#define Lseq  1024
#define Pdim  64
#define Hdim  256
#define OUTD  128

// 16 clusters x 8 CTAs. Cluster: 4 batch rows. CTA: 32 hidden units (96 gate rows).
// 768 threads: thread = (row 0..95, half 0..1, batch 0..3); each computes a half-dot,
// halves combined via shfl_xor(4).
#define CLUSTER  8
#define B_TILE   4
#define NTHREADS 768
#define ROWS     96
#define UNITS    32
// padded layouts: halves offset by +4 words so hf0/hf1 lanes hit different banks
#define WH_PAD   264          // 128 | pad4 | 128 | pad4
#define WH_HALF  132
#define WX_PAD   72           // 32 | pad4 | 32 | pad4
#define WX_HALF  36
#define HB_PAD   264
#define PARTS    12           // final-GEMM K-split (768/64)

struct __align__(16) Smem {
    float Wx[ROWS * WX_PAD];        // encoder W_ih slice (96x64, padded halves)
    float Wh[ROWS * WH_PAD];        // W_hh slice (96x256, padded); reused for decoder
    float hb[2][B_TILE][HB_PAD];    // double-buffered hidden state (padded at 128)
    float xb[2][B_TILE][WX_PAD];    // double-buffered staged x_t (padded at 32)
    float Asm[ROWS * B_TILE];       // input-gate partials
    float Gsm[ROWS * B_TILE];       // hidden-gate partials
    float giD[ROWS * B_TILE];       // decoder constant input gates
    float wa[Hdim];                 // attention hidden weight row
    float wdec[Hdim];               // decoder output weight
    float bA[ROWS];
    float bG[ROWS];
    float yb[Lseq * B_TILE];        // decoder outputs y[i][b]
    float red[64 * PARTS];          // final GEMM reduction scratch
};

__device__ __forceinline__ uint32_t s2u(const void* p) {
    uint32_t a;
    asm("{ .reg .u64 t; cvta.to.shared.u64 t, %1; cvt.u32.u64 %0, t; }"
        : "=r"(a) : "l"(p));
    return a;
}

__device__ __forceinline__ uint32_t mapa_r(uint32_t la, int r) {
    uint32_t ra;
    asm("mapa.shared::cluster.u32 %0, %1, %2;" : "=r"(ra) : "r"(la), "r"(r));
    return ra;
}

__device__ __forceinline__ void st_clu(uint32_t ra, float v) {
    asm volatile("st.shared::cluster.b32 [%0], %1;"
                 :: "r"(ra), "r"(__float_as_uint(v)) : "memory");
}

__device__ __forceinline__ void csync() {
    asm volatile("barrier.cluster.arrive.aligned;" ::: "memory");
    asm volatile("barrier.cluster.wait.aligned;" ::: "memory");
}

__device__ __forceinline__ float sigf(float v) { return 1.0f / (1.0f + expf(-v)); }

// Packed-fp32 half-dot over NF4 float4 chunks (NF4*4 floats) using fma.rn.f32x2.
// 4 independent packed accumulator chains. W and v must be 16B-aligned SMEM.
// NF4 must be even.
template<int NF4>
__device__ __forceinline__ float dotp(const float* __restrict__ W,
                                      const float* __restrict__ v) {
    const ulonglong2* w2 = (const ulonglong2*)W;
    const ulonglong2* v2 = (const ulonglong2*)v;
    unsigned long long a0 = 0ull, a1 = 0ull, a2 = 0ull, a3 = 0ull;
#pragma unroll
    for (int k = 0; k < NF4; k += 2) {
        ulonglong2 w = w2[k],     x = v2[k];
        asm("fma.rn.f32x2 %0, %1, %2, %0;" : "+l"(a0) : "l"(w.x), "l"(x.x));
        asm("fma.rn.f32x2 %0, %1, %2, %0;" : "+l"(a1) : "l"(w.y), "l"(x.y));
        ulonglong2 wb = v2 == w2 ? w : w2[k + 1];  // keep simple: reload below
        ulonglong2 w1 = w2[k + 1], x1 = v2[k + 1];
        asm("fma.rn.f32x2 %0, %1, %2, %0;" : "+l"(a2) : "l"(w1.x), "l"(x1.x));
        asm("fma.rn.f32x2 %0, %1, %2, %0;" : "+l"(a3) : "l"(w1.y), "l"(x1.y));
        (void)wb;
    }
    float s0 = __uint_as_float((unsigned)(a0 & 0xffffffffull))
             + __uint_as_float((unsigned)(a0 >> 32));
    float s1 = __uint_as_float((unsigned)(a1 & 0xffffffffull))
             + __uint_as_float((unsigned)(a1 >> 32));
    float s2 = __uint_as_float((unsigned)(a2 & 0xffffffffull))
             + __uint_as_float((unsigned)(a2 >> 32));
    float s3 = __uint_as_float((unsigned)(a3 & 0xffffffffull))
             + __uint_as_float((unsigned)(a3 >> 32));
    return (s0 + s1) + (s2 + s3);
}

__global__ void __cluster_dims__(CLUSTER, 1, 1) __launch_bounds__(NTHREADS, 1)
attn_net_kernel(const float* __restrict__ x,
                const float* __restrict__ Wihe, const float* __restrict__ Whhe,
                const float* __restrict__ bihe, const float* __restrict__ bhhe,
                const float* __restrict__ Wihd, const float* __restrict__ Whhd,
                const float* __restrict__ bihd, const float* __restrict__ bhhd,
                const float* __restrict__ Wdec, const float* __restrict__ bdec_p,
                const float* __restrict__ Wattn, const float* __restrict__ battn,
                const float* __restrict__ Wout, const float* __restrict__ bout,
                float* __restrict__ out)
{
    extern __shared__ char smem_raw[];
    Smem& S = *reinterpret_cast<Smem*>(smem_raw);

    const int tid = threadIdx.x;
    uint32_t rank;
    asm("mov.u32 %0, %%cluster_ctarank;" : "=r"(rank));
    const int g   = blockIdx.x >> 3;        // cluster id 0..15
    const int b0  = g * B_TILE;             // batch base
    const int U0  = (int)rank * UNITS;      // hidden-unit base for this CTA
    const int PADU = U0 + ((int)rank >= 4 ? 4 : 0);  // padded index into hb rows
    const int row = tid >> 3;               // 0..95
    const int hf  = (tid >> 2) & 1;         // half 0/1
    const int bb  = tid & 3;                // batch 0..3

    // ---------------- Phase 0: load weight slices (padded layouts) ----------------
    for (int idx = tid; idx < ROWS * Pdim; idx += NTHREADS) {
        int lr = idx >> 6, k = idx & 63;
        int grow = (lr >> 5) * Hdim + U0 + (lr & 31);
        S.Wx[lr * WX_PAD + k + (k >= 32 ? 4 : 0)] = Wihe[grow * Pdim + k];
    }
    for (int idx = tid; idx < ROWS * Hdim; idx += NTHREADS) {
        int lr = idx >> 8, k = idx & 255;
        int grow = (lr >> 5) * Hdim + U0 + (lr & 31);
        S.Wh[lr * WH_PAD + k + (k >= 128 ? 4 : 0)] = Whhe[grow * Hdim + k];
    }
    for (int idx = tid; idx < ROWS; idx += NTHREADS) {
        int grow = (idx >> 5) * Hdim + U0 + (idx & 31);
        S.bA[idx] = bihe[grow];
        S.bG[idx] = bhhe[grow];
    }
    for (int idx = tid; idx < Hdim; idx += NTHREADS) {
        S.wa[idx]   = Wattn[Hdim + idx];   // W_attn[0, H + idx]
        S.wdec[idx] = Wdec[idx];           // W_dec_out[0, idx]
    }
    for (int idx = tid; idx < 2 * B_TILE * HB_PAD; idx += NTHREADS)
        ((float*)S.hb)[idx] = 0.f;
    __syncthreads();
    csync();

    // Remote DSMEM addresses for the per-step h broadcast (combine threads only):
    uint32_t raddr[2][CLUSTER];
    if (tid < UNITS * B_TILE) {
        int u = tid >> 2, b = tid & 3;
#pragma unroll
        for (int buf = 0; buf < 2; buf++) {
            uint32_t la = s2u(&S.hb[buf][b][PADU + u]);
#pragma unroll
            for (int pr = 0; pr < CLUSTER; pr++)
                raddr[buf][pr] = mapa_r(la, pr);
        }
    }

    // Per-warp (warps 0-3 = batches 0-3) online-softmax state in registers.
    float m_run = -3.0e38f, Z_run = 0.f, C_run = 0.f;

    // ---------------- Phase 1: encoder GRU + online-softmax attention ----------------
    // Stage x_0 into xb[0]; prefetch x_1 into rx.
    float rx = 0.f;
    if (tid < 256) {
        rx = x[(b0 + (tid >> 6)) * (Lseq * Pdim) + (tid & 63)];
        int e = tid & 63;
        S.xb[0][tid >> 6][e + (e >= 32 ? 4 : 0)] = rx;
    }
    __syncthreads();
    if (tid < 256)
        rx = x[(b0 + (tid >> 6)) * (Lseq * Pdim) + Pdim + (tid & 63)];

    for (int t = 0; t < Lseq; t++) {
        const int cur = t & 1, nxt = cur ^ 1;

        // half-GEMVs: thread owns (row, half, batch); shfl_xor(4) joins halves
        float ap = dotp<8> (&S.Wx[row * WX_PAD + hf * WX_HALF], &S.xb[cur][bb][hf * WX_HALF]);
        float gp = dotp<32>(&S.Wh[row * WH_PAD + hf * WH_HALF], &S.hb[cur][bb][hf * WH_HALF]);
        ap += __shfl_xor_sync(0xffffffffu, ap, 4);
        gp += __shfl_xor_sync(0xffffffffu, gp, 4);
        if (hf == 0) {
            S.Asm[row * 4 + bb] = S.bA[row] + ap;
            S.Gsm[row * 4 + bb] = S.bG[row] + gp;
        }
        // stage x_{t+1} before the bar (bar covers both Asm/Gsm and xb)
        if (tid < 256) {
            int e = tid & 63;
            S.xb[nxt][tid >> 6][e + (e >= 32 ? 4 : 0)] = rx;
        }
        __syncthreads();
        if (tid < 256 && (t + 2) < Lseq)
            rx = x[(b0 + (tid >> 6)) * (Lseq * Pdim) + (t + 2) * Pdim + (tid & 63)];

        // combine gates, push new hidden slice to all 8 CTAs
        if (tid < UNITS * B_TILE) {
            int u = tid >> 2, b = tid & 3;
            float r = sigf(S.Asm[u * 4 + b] + S.Gsm[u * 4 + b]);
            float z = sigf(S.Asm[(32 + u) * 4 + b] + S.Gsm[(32 + u) * 4 + b]);
            float n = tanhf(S.Asm[(64 + u) * 4 + b] + r * S.Gsm[(64 + u) * 4 + b]);
            float hn = (1.f - z) * n + z * S.hb[cur][b][PADU + u];
#pragma unroll
            for (int pr = 0; pr < CLUSTER; pr++) st_clu(raddr[nxt][pr], hn);
        }
        csync();

        // warp w owns batch w: h_proj + online softmax + context, in registers.
        // Overlaps next step's GEMV in warps 4..23 (they run to the next bar).
        if (tid < 128) {
            int w = tid >> 5, l = tid & 31;
            float p = 0.f;
#pragma unroll
            for (int j = l; j < 128; j += 32) p += S.hb[nxt][w][j] * S.wa[j];
#pragma unroll
            for (int j = 128 + l; j < 256; j += 32) p += S.hb[nxt][w][j + 4] * S.wa[j];
#pragma unroll
            for (int o = 16; o > 0; o >>= 1) p += __shfl_xor_sync(0xffffffffu, p, o);
            float mn  = fmaxf(m_run, p);
            float sc  = expf(m_run - mn);
            float wgt = expf(p - mn);
            Z_run = Z_run * sc + wgt;
            m_run = mn;
            C_run = C_run * sc + wgt * S.hb[nxt][w][PADU + l];
        }
    }
    // last hidden state s0 lives in hb[0]

    // ---------------- Phase 1.5: context c, decoder constant gates ----------------
    if (tid < 128) {
        int w = tid >> 5, l = tid & 31;
        float cv = C_run / Z_run;
        uint32_t la = s2u(&S.hb[1][w][PADU + l]);
#pragma unroll
        for (int pr = 0; pr < CLUSTER; pr++) st_clu(mapa_r(la, pr), cv);
    }
    csync();

    // decoder input weights -> Wh region; giD = W_ih_d . c + b_ih_d
    for (int idx = tid; idx < ROWS * Hdim; idx += NTHREADS) {
        int lr = idx >> 8, k = idx & 255;
        int grow = (lr >> 5) * Hdim + U0 + (lr & 31);
        S.Wh[lr * WH_PAD + k + (k >= 128 ? 4 : 0)] = Wihd[grow * Hdim + k];
    }
    for (int idx = tid; idx < ROWS; idx += NTHREADS) {
        int grow = (idx >> 5) * Hdim + U0 + (idx & 31);
        S.bA[idx] = bihd[grow];
        S.bG[idx] = bhhd[grow];
    }
    __syncthreads();
    {
        float gp = dotp<32>(&S.Wh[row * WH_PAD + hf * WH_HALF], &S.hb[1][bb][hf * WH_HALF]);
        gp += __shfl_xor_sync(0xffffffffu, gp, 4);
        if (hf == 0) S.giD[row * 4 + bb] = S.bA[row] + gp;
    }
    __syncthreads();

    // decoder recurrent weights
    for (int idx = tid; idx < ROWS * Hdim; idx += NTHREADS) {
        int lr = idx >> 8, k = idx & 255;
        int grow = (lr >> 5) * Hdim + U0 + (lr & 31);
        S.Wh[lr * WH_PAD + k + (k >= 128 ? 4 : 0)] = Whhd[grow * Hdim + k];
    }
    const float bdec = bdec_p[0];
    __syncthreads();
    csync();

    // ---------------- Phase 2: decoder GRU (constant input gates) ----------------
    for (int i = 0; i < Lseq; i++) {
        const int cur = i & 1, nxt = cur ^ 1;

        float gp = dotp<32>(&S.Wh[row * WH_PAD + hf * WH_HALF], &S.hb[cur][bb][hf * WH_HALF]);
        gp += __shfl_xor_sync(0xffffffffu, gp, 4);
        if (hf == 0) S.Gsm[row * 4 + bb] = S.bG[row] + gp;
        __syncthreads();

        if (tid < 128) {
            int u = tid >> 2, b = tid & 3;
            float r = sigf(S.giD[u * 4 + b] + S.Gsm[u * 4 + b]);
            float z = sigf(S.giD[(32 + u) * 4 + b] + S.Gsm[(32 + u) * 4 + b]);
            float n = tanhf(S.giD[(64 + u) * 4 + b] + r * S.Gsm[(64 + u) * 4 + b]);
            float sn = (1.f - z) * n + z * S.hb[cur][b][PADU + u];
#pragma unroll
            for (int pr = 0; pr < CLUSTER; pr++) st_clu(raddr[nxt][pr], sn);
        }
        csync();

        // y_i[b] = sigmoid(s_new . w_dec + b_dec); overlaps next step's GEMV
        if (tid < 128) {
            int w = tid >> 5, l = tid & 31;
            float p = 0.f;
#pragma unroll
            for (int j = l; j < 128; j += 32) p += S.hb[nxt][w][j] * S.wdec[j];
#pragma unroll
            for (int j = 128 + l; j < 256; j += 32) p += S.hb[nxt][w][j + 4] * S.wdec[j];
#pragma unroll
            for (int o = 16; o > 0; o >>= 1) p += __shfl_xor_sync(0xffffffffu, p, o);
            if (l == 0) S.yb[i * 4 + w] = sigf(p + bdec);
        }
    }

    // ---------------- Phase 3: out = y @ W_out^T + b_out ----------------
    __syncthreads();
    {
        int part = tid >> 6;            // 0..11, K-split
        int ob   = tid & 63;            // 16 o-rows x 4 batches
        int o    = (int)rank * 16 + (ob >> 2);
        int b    = ob & 3;
        float acc = 0.f;
        for (int i = part; i < Lseq; i += PARTS)
            acc += S.yb[i * 4 + b] * Wout[o * Lseq + i];
        S.red[ob * PARTS + part] = acc;
    }
    __syncthreads();
    if (tid < 64) {
        int o = (int)rank * 16 + (tid >> 2);
        int b = tid & 3;
        float s = bout[o];
#pragma unroll
        for (int p6 = 0; p6 < PARTS; p6++) s += S.red[tid * PARTS + p6];
        out[(b0 + b) * OUTD + o] = s;
    }
}

extern "C" void kernel_launch(void* const* d_in, const int* in_sizes, int n_in,
                              void* d_out, int out_size) {
    (void)in_sizes; (void)n_in; (void)out_size;
    cudaFuncSetAttribute(attn_net_kernel,
                         cudaFuncAttributeMaxDynamicSharedMemorySize,
                         (int)sizeof(Smem));
    attn_net_kernel<<<128, NTHREADS, sizeof(Smem)>>>(
        (const float*)d_in[0],  (const float*)d_in[1],  (const float*)d_in[2],
        (const float*)d_in[3],  (const float*)d_in[4],  (const float*)d_in[5],
        (const float*)d_in[6],  (const float*)d_in[7],  (const float*)d_in[8],
        (const float*)d_in[9],  (const float*)d_in[10], (const float*)d_in[11],
        (const float*)d_in[12], (const float*)d_in[13], (const float*)d_in[14],
        (float*)d_out);
}

// round 11
// speedup vs baseline: 1.7549x; 1.7344x over previous
#include <cuda_runtime.h>
#include <cstdint>

// Problem dims
#define Lseq  1024
#define Pdim  64
#define Hdim  256
#define OUTD  128
#define GI3H  768      // 3*Hdim

// 32 clusters x 4 CTAs. Cluster: 2 batch rows. CTA: 64 hidden units (192 gate rows).
// 768 threads: thread = (row 0..191, half 0..1, batch 0..1).
#define CLUSTER  4
#define B_TILE   2
#define NTHREADS 768
#define ROWSL    192
#define UNITSL   64
#define WH_PAD   260       // row stride: 260 mod 32 = 4 -> 8 warp-rows tile all bank groups
#define WH_HALF  128
#define HB_PAD   268       // batch stride mod 32 = 12; half offset 132 (mod 32 = 4)
#define HB_HALF  132
#define PARTS    12

// Precomputed encoder input gates: gi[t*64 + b][grow], grow = q*256 + u
__device__ float g_gi[(size_t)Lseq * 64 * GI3H];   // 201 MB scratch

struct __align__(16) Smem {
    float Wh[ROWSL * WH_PAD];       // 192x256 weight slice (enc Whh, then dec Wih, dec Whh)
    float hb[2][B_TILE][HB_PAD];    // double-buffered hidden state
    float Gsm[ROWSL * B_TILE];      // hidden-gate partials
    float giD[ROWSL * B_TILE];      // decoder constant input gates
    float wa[Hdim];                 // attention hidden weight row
    float wdec[Hdim];               // decoder output weight
    float bG[ROWSL];                // recurrent bias (bhh)
    float yb[Lseq * B_TILE];        // decoder outputs
    float red[768];                 // scratch: c-broadcast staging / dec ih bias / final GEMM
};

__device__ __forceinline__ uint32_t s2u(const void* p) {
    uint32_t a;
    asm("{ .reg .u64 t; cvta.to.shared.u64 t, %1; cvt.u32.u64 %0, t; }"
        : "=r"(a) : "l"(p));
    return a;
}

__device__ __forceinline__ uint32_t mapa_r(uint32_t la, int r) {
    uint32_t ra;
    asm("mapa.shared::cluster.u32 %0, %1, %2;" : "=r"(ra) : "r"(la), "r"(r));
    return ra;
}

__device__ __forceinline__ void st_clu64(uint32_t ra, float a, float b) {
    unsigned long long v;
    asm("mov.b64 %0, {%1, %2};" : "=l"(v)
        : "r"(__float_as_uint(a)), "r"(__float_as_uint(b)));
    asm volatile("st.shared::cluster.b64 [%0], %1;" :: "r"(ra), "l"(v) : "memory");
}

__device__ __forceinline__ void csync() {
    asm volatile("barrier.cluster.arrive.aligned;" ::: "memory");
    asm volatile("barrier.cluster.wait.aligned;" ::: "memory");
}

__device__ __forceinline__ float sigf(float v) { return 1.0f / (1.0f + expf(-v)); }

// Packed-fp32 half-dot over 32 float4 chunks (128 floats) using fma.rn.f32x2,
// 4 independent packed accumulator chains. 16B-aligned SMEM pointers required.
__device__ __forceinline__ float dotp128(const float* __restrict__ W,
                                         const float* __restrict__ v) {
    const ulonglong2* w2 = (const ulonglong2*)W;
    const ulonglong2* v2 = (const ulonglong2*)v;
    unsigned long long a0 = 0ull, a1 = 0ull, a2 = 0ull, a3 = 0ull;
#pragma unroll
    for (int k = 0; k < 32; k += 2) {
        ulonglong2 w = w2[k],     x = v2[k];
        asm("fma.rn.f32x2 %0, %1, %2, %0;" : "+l"(a0) : "l"(w.x), "l"(x.x));
        asm("fma.rn.f32x2 %0, %1, %2, %0;" : "+l"(a1) : "l"(w.y), "l"(x.y));
        ulonglong2 w1 = w2[k + 1], x1 = v2[k + 1];
        asm("fma.rn.f32x2 %0, %1, %2, %0;" : "+l"(a2) : "l"(w1.x), "l"(x1.x));
        asm("fma.rn.f32x2 %0, %1, %2, %0;" : "+l"(a3) : "l"(w1.y), "l"(x1.y));
    }
    float s0 = __uint_as_float((unsigned)(a0 & 0xffffffffull))
             + __uint_as_float((unsigned)(a0 >> 32));
    float s1 = __uint_as_float((unsigned)(a1 & 0xffffffffull))
             + __uint_as_float((unsigned)(a1 >> 32));
    float s2 = __uint_as_float((unsigned)(a2 & 0xffffffffull))
             + __uint_as_float((unsigned)(a2 >> 32));
    float s3 = __uint_as_float((unsigned)(a3 & 0xffffffffull))
             + __uint_as_float((unsigned)(a3 >> 32));
    return (s0 + s1) + (s2 + s3);
}

// ---------------- Pre-kernel: gi[t][b][o] = b_ih_e[o] + x[b,t,:] . W_ih_e[o,:] ----
__global__ void __launch_bounds__(256, 1)
gi_kernel(const float* __restrict__ x,
          const float* __restrict__ Wihe,
          const float* __restrict__ bihe)
{
    __shared__ float xs[64 * Pdim];            // 64 batches x 64 inputs for this t
    const int t  = blockIdx.x;                 // 0..1023
    const int o  = blockIdx.y * 256 + threadIdx.x;   // 0..767

    float4 wr[16];
    const float4* Wr = (const float4*)(Wihe + o * Pdim);
#pragma unroll
    for (int k = 0; k < 16; k++) wr[k] = Wr[k];
    const float bia = bihe[o];

    for (int idx = threadIdx.x; idx < 64 * Pdim; idx += 256) {
        int b = idx >> 6, p = idx & 63;
        xs[idx] = x[((size_t)b * Lseq + t) * Pdim + p];
    }
    __syncthreads();

    for (int b = 0; b < 64; b++) {
        const float4* xr = (const float4*)(xs + b * Pdim);
        float a0 = bia, a1 = 0.f, a2 = 0.f, a3 = 0.f;
#pragma unroll
        for (int k = 0; k < 16; k++) {
            float4 w = wr[k], xx = xr[k];
            a0 = fmaf(w.x, xx.x, a0); a1 = fmaf(w.y, xx.y, a1);
            a2 = fmaf(w.z, xx.z, a2); a3 = fmaf(w.w, xx.w, a3);
        }
        g_gi[((size_t)t * 64 + b) * GI3H + o] = (a0 + a1) + (a2 + a3);
    }
}

// ---------------- Main recurrent kernel ----------------
__global__ void __cluster_dims__(CLUSTER, 1, 1) __launch_bounds__(NTHREADS, 1)
attn_net_kernel(const float* __restrict__ x,
                const float* __restrict__ Wihe, const float* __restrict__ Whhe,
                const float* __restrict__ bihe, const float* __restrict__ bhhe,
                const float* __restrict__ Wihd, const float* __restrict__ Whhd,
                const float* __restrict__ bihd, const float* __restrict__ bhhd,
                const float* __restrict__ Wdec, const float* __restrict__ bdec_p,
                const float* __restrict__ Wattn, const float* __restrict__ battn,
                const float* __restrict__ Wout, const float* __restrict__ bout,
                float* __restrict__ out)
{
    extern __shared__ char smem_raw[];
    Smem& S = *reinterpret_cast<Smem*>(smem_raw);

    const int tid = threadIdx.x;
    uint32_t rank;
    asm("mov.u32 %0, %%cluster_ctarank;" : "=r"(rank));
    const int g    = blockIdx.x >> 2;          // cluster id 0..31
    const int b0   = g * B_TILE;               // batch base
    const int U0   = (int)rank * UNITSL;       // hidden-unit base
    const int U0pad= U0 + (U0 >= 128 ? 4 : 0); // padded hb index base
    const int row  = tid >> 2;                 // 0..191
    const int hf   = (tid >> 1) & 1;           // half 0/1
    const int bb   = tid & 1;                  // batch 0/1
    const int ul   = tid >> 1;                 // combine unit (tid<128)
    const int cb   = tid & 1;                  // combine batch

    // ---------------- Phase 0: encoder recurrent weights ----------------
    for (int idx = tid; idx < ROWSL * Hdim; idx += NTHREADS) {
        int lr = idx >> 8, k = idx & 255;
        int grow = (lr >> 6) * Hdim + U0 + (lr & 63);
        S.Wh[lr * WH_PAD + k] = Whhe[grow * Hdim + k];
    }
    for (int idx = tid; idx < ROWSL; idx += NTHREADS) {
        int grow = (idx >> 6) * Hdim + U0 + (idx & 63);
        S.bG[idx] = bhhe[grow];
    }
    for (int idx = tid; idx < Hdim; idx += NTHREADS) {
        S.wa[idx]   = Wattn[Hdim + idx];
        S.wdec[idx] = Wdec[idx];
    }
    for (int idx = tid; idx < 2 * B_TILE * HB_PAD; idx += NTHREADS)
        ((float*)S.hb)[idx] = 0.f;
    __syncthreads();
    csync();

    // Remote DSMEM addresses for the packed h broadcast (store threads: ul%4==0)
    uint32_t raddr[2][CLUSTER];
    if (tid < 128 && !(ul & 3)) {
#pragma unroll
        for (int buf = 0; buf < 2; buf++) {
            uint32_t la = s2u(&S.hb[buf][cb][U0pad + ul]);
#pragma unroll
            for (int pr = 0; pr < CLUSTER; pr++)
                raddr[buf][pr] = mapa_r(la, pr);
        }
    }

    // gi prefetch (combine threads): 3 gate values per step, one step ahead
    const float* giP = nullptr;
    float g0 = 0.f, g1 = 0.f, g2 = 0.f;
    if (tid < 128) {
        giP = g_gi + (size_t)(b0 + cb) * GI3H + U0 + ul;
        g0 = giP[0]; g1 = giP[256]; g2 = giP[512];
    }

    // Warps 0-1 = batches 0-1: online-softmax state in registers.
    float m_run = -3.0e38f, Z_run = 0.f, C0 = 0.f, C1 = 0.f;

    // ---------------- Phase 1: encoder GRU + online-softmax attention ----------------
    for (int t = 0; t < Lseq; t++) {
        const int cur = t & 1, nxt = cur ^ 1;

        float n0 = 0.f, n1 = 0.f, n2 = 0.f;
        if (tid < 128 && (t + 1) < Lseq) {
            const float* p = giP + (size_t)(t + 1) * (64 * GI3H);
            n0 = p[0]; n1 = p[256]; n2 = p[512];
        }

        // hidden GEMV: half-dot joined via shfl_xor(2)
        float gp = dotp128(&S.Wh[row * WH_PAD + hf * WH_HALF],
                           &S.hb[cur][bb][hf * HB_HALF]);
        gp += __shfl_xor_sync(0xffffffffu, gp, 2);
        if (hf == 0) S.Gsm[row * 2 + bb] = S.bG[row] + gp;
        __syncthreads();

        // combine gates; pack 4 units and broadcast b64 pairs to all 4 CTAs
        if (tid < 128) {
            float r = sigf(g0 + S.Gsm[ul * 2 + cb]);
            float z = sigf(g1 + S.Gsm[(64 + ul) * 2 + cb]);
            float n = tanhf(g2 + r * S.Gsm[(128 + ul) * 2 + cb]);
            float hn = (1.f - z) * n + z * S.hb[cur][cb][U0pad + ul];
            float v1 = __shfl_down_sync(0xffffffffu, hn, 2);
            float v2 = __shfl_down_sync(0xffffffffu, hn, 4);
            float v3 = __shfl_down_sync(0xffffffffu, hn, 6);
            if (!(ul & 3)) {
#pragma unroll
                for (int pr = 0; pr < CLUSTER; pr++) {
                    st_clu64(raddr[nxt][pr],     hn, v1);
                    st_clu64(raddr[nxt][pr] + 8, v2, v3);
                }
            }
            g0 = n0; g1 = n1; g2 = n2;
        }
        csync();

        // warp w owns batch w: h_proj + online softmax + context (overlaps next GEMV)
        if (tid < 64) {
            int w = tid >> 5, l = tid & 31;
            const float* hr = S.hb[nxt][w];
            float p = 0.f;
#pragma unroll
            for (int j = l; j < 128; j += 32) p += hr[j] * S.wa[j];
#pragma unroll
            for (int j = 128 + l; j < 256; j += 32) p += hr[j + 4] * S.wa[j];
#pragma unroll
            for (int o = 16; o > 0; o >>= 1) p += __shfl_xor_sync(0xffffffffu, p, o);
            float mn  = fmaxf(m_run, p);
            float sc  = expf(m_run - mn);
            float wgt = expf(p - mn);
            Z_run = Z_run * sc + wgt;
            m_run = mn;
            C0 = C0 * sc + wgt * hr[U0pad + l];
            C1 = C1 * sc + wgt * hr[U0pad + 32 + l];
        }
    }
    // final hidden state s0 lives in hb[0]

    // ---------------- Phase 1.5: context c -> hb[1], decoder constant gates ----------------
    __syncthreads();
    if (tid < 64) {
        int w = tid >> 5, l = tid & 31;
        float iz = 1.f / Z_run;
        S.red[w * 64 + l]      = C0 * iz;
        S.red[w * 64 + 32 + l] = C1 * iz;
    }
    __syncthreads();
    if (tid < 128 && !(ul & 3)) {
        float c0 = S.red[cb * 64 + ul],     c1 = S.red[cb * 64 + ul + 1];
        float c2 = S.red[cb * 64 + ul + 2], c3 = S.red[cb * 64 + ul + 3];
#pragma unroll
        for (int pr = 0; pr < CLUSTER; pr++) {
            st_clu64(raddr[1][pr],     c0, c1);
            st_clu64(raddr[1][pr] + 8, c2, c3);
        }
    }
    csync();

    // decoder input weights + bias; giD = W_ih_d . c + b_ih_d
    for (int idx = tid; idx < ROWSL * Hdim; idx += NTHREADS) {
        int lr = idx >> 8, k = idx & 255;
        int grow = (lr >> 6) * Hdim + U0 + (lr & 63);
        S.Wh[lr * WH_PAD + k] = Wihd[grow * Hdim + k];
    }
    for (int idx = tid; idx < ROWSL; idx += NTHREADS) {
        int grow = (idx >> 6) * Hdim + U0 + (idx & 63);
        S.red[idx] = bihd[grow];
        S.bG[idx]  = bhhd[grow];
    }
    __syncthreads();
    {
        float gp = dotp128(&S.Wh[row * WH_PAD + hf * WH_HALF],
                           &S.hb[1][bb][hf * HB_HALF]);
        gp += __shfl_xor_sync(0xffffffffu, gp, 2);
        if (hf == 0) S.giD[row * 2 + bb] = S.red[row] + gp;
    }
    __syncthreads();

    // decoder recurrent weights
    for (int idx = tid; idx < ROWSL * Hdim; idx += NTHREADS) {
        int lr = idx >> 8, k = idx & 255;
        int grow = (lr >> 6) * Hdim + U0 + (lr & 63);
        S.Wh[lr * WH_PAD + k] = Whhd[grow * Hdim + k];
    }
    const float bdec = bdec_p[0];
    __syncthreads();
    csync();

    // ---------------- Phase 2: decoder GRU (constant input gates) ----------------
    for (int i = 0; i < Lseq; i++) {
        const int cur = i & 1, nxt = cur ^ 1;

        float gp = dotp128(&S.Wh[row * WH_PAD + hf * WH_HALF],
                           &S.hb[cur][bb][hf * HB_HALF]);
        gp += __shfl_xor_sync(0xffffffffu, gp, 2);
        if (hf == 0) S.Gsm[row * 2 + bb] = S.bG[row] + gp;
        __syncthreads();

        if (tid < 128) {
            float r = sigf(S.giD[ul * 2 + cb] + S.Gsm[ul * 2 + cb]);
            float z = sigf(S.giD[(64 + ul) * 2 + cb] + S.Gsm[(64 + ul) * 2 + cb]);
            float n = tanhf(S.giD[(128 + ul) * 2 + cb] + r * S.Gsm[(128 + ul) * 2 + cb]);
            float sn = (1.f - z) * n + z * S.hb[cur][cb][U0pad + ul];
            float v1 = __shfl_down_sync(0xffffffffu, sn, 2);
            float v2 = __shfl_down_sync(0xffffffffu, sn, 4);
            float v3 = __shfl_down_sync(0xffffffffu, sn, 6);
            if (!(ul & 3)) {
#pragma unroll
                for (int pr = 0; pr < CLUSTER; pr++) {
                    st_clu64(raddr[nxt][pr],     sn, v1);
                    st_clu64(raddr[nxt][pr] + 8, v2, v3);
                }
            }
        }
        csync();

        // y_i[b] = sigmoid(s_new . w_dec + b_dec); overlaps next step's GEMV
        if (tid < 64) {
            int w = tid >> 5, l = tid & 31;
            const float* hr = S.hb[nxt][w];
            float p = 0.f;
#pragma unroll
            for (int j = l; j < 128; j += 32) p += hr[j] * S.wdec[j];
#pragma unroll
            for (int j = 128 + l; j < 256; j += 32) p += hr[j + 4] * S.wdec[j];
#pragma unroll
            for (int o = 16; o > 0; o >>= 1) p += __shfl_xor_sync(0xffffffffu, p, o);
            if (l == 0) S.yb[i * 2 + w] = sigf(p + bdec);
        }
    }

    // ---------------- Phase 3: out = y @ W_out^T + b_out ----------------
    __syncthreads();
    {
        int part = tid >> 6;                // 0..11
        int ob   = tid & 63;                // 32 o-rows x 2 batches
        int o    = (int)rank * 32 + (ob >> 1);
        int b    = ob & 1;
        float acc = 0.f;
        for (int i = part; i < Lseq; i += PARTS)
            acc += S.yb[i * 2 + b] * Wout[o * Lseq + i];
        S.red[ob * PARTS + part] = acc;
    }
    __syncthreads();
    if (tid < 64) {
        int o = (int)rank * 32 + (tid >> 1);
        int b = tid & 1;
        float s = bout[o];
#pragma unroll
        for (int p6 = 0; p6 < PARTS; p6++) s += S.red[tid * PARTS + p6];
        out[(b0 + b) * OUTD + o] = s;
    }
}

extern "C" void kernel_launch(void* const* d_in, const int* in_sizes, int n_in,
                              void* d_out, int out_size) {
    (void)in_sizes; (void)n_in; (void)out_size;

    // Pre-kernel: gi = x @ W_ih_e^T + b_ih_e for all timesteps
    gi_kernel<<<dim3(Lseq, 3), 256>>>(
        (const float*)d_in[0], (const float*)d_in[1], (const float*)d_in[3]);

    cudaFuncSetAttribute(attn_net_kernel,
                         cudaFuncAttributeMaxDynamicSharedMemorySize,
                         (int)sizeof(Smem));
    attn_net_kernel<<<128, NTHREADS, sizeof(Smem)>>>(
        (const float*)d_in[0],  (const float*)d_in[1],  (const float*)d_in[2],
        (const float*)d_in[3],  (const float*)d_in[4],  (const float*)d_in[5],
        (const float*)d_in[6],  (const float*)d_in[7],  (const float*)d_in[8],
        (const float*)d_in[9],  (const float*)d_in[10], (const float*)d_in[11],
        (const float*)d_in[12], (const float*)d_in[13], (const float*)d_in[14],
        (float*)d_out);
}

// round 12
// speedup vs baseline: 2.2237x; 1.2671x over previous
#include <cuda_runtime.h>
#include <cstdint>

// Problem dims
#define Lseq  1024
#define Pdim  64
#define Hdim  256
#define OUTD  128
#define GI3H  768      // 3*Hdim

// 32 clusters x 4 CTAs. Cluster: 2 batch rows. CTA: 64 hidden units (192 gate rows).
// 512 threads: tid = u*8 + bb*4 + q. Thread computes all 3 gate rows (u, 64+u, 128+u)
// as quarter-dots (64 cols, bank-interleaved chunks); quarters joined via shfl_xor(1,2).
#define CLUSTER  4
#define B_TILE   2
#define NTHREADS 512
#define ROWSL    192
#define UNITSL   64
#define WH_PAD   260       // 256 + pad4 at col 128; row stride mod 32 = 4
#define HB_PAD   268
#define PARTS    8

// Precomputed encoder input gates: gi[t*64 + b][grow], grow = gate*256 + U0 + u
__device__ float g_gi[(size_t)Lseq * 64 * GI3H];   // 201 MB scratch

struct __align__(16) Smem {
    float Wh[ROWSL * WH_PAD];       // 192x256 weight slice (enc Whh -> dec Wih -> dec Whh)
    float hb[2][B_TILE][HB_PAD];    // double-buffered hidden state (pad4 at 128)
    float wa[Hdim];                 // attention hidden weight row
    float wdec[Hdim];               // decoder output weight
    float yb[Lseq * B_TILE];        // decoder outputs
    float red[768];                 // staging: context / final GEMM reduction
};

__device__ __forceinline__ uint32_t s2u(const void* p) {
    uint32_t a;
    asm("{ .reg .u64 t; cvta.to.shared.u64 t, %1; cvt.u32.u64 %0, t; }"
        : "=r"(a) : "l"(p));
    return a;
}

__device__ __forceinline__ uint32_t mapa_r(uint32_t la, int r) {
    uint32_t ra;
    asm("mapa.shared::cluster.u32 %0, %1, %2;" : "=r"(ra) : "r"(la), "r"(r));
    return ra;
}

__device__ __forceinline__ void st_clu64(uint32_t ra, float a, float b) {
    unsigned long long v;
    asm("mov.b64 %0, {%1, %2};" : "=l"(v)
        : "r"(__float_as_uint(a)), "r"(__float_as_uint(b)));
    asm volatile("st.shared::cluster.b64 [%0], %1;" :: "r"(ra), "l"(v) : "memory");
}

__device__ __forceinline__ void csync() {
    asm volatile("barrier.cluster.arrive.aligned;" ::: "memory");
    asm volatile("barrier.cluster.wait.aligned;" ::: "memory");
}

__device__ __forceinline__ float sigf(float v) { return 1.0f / (1.0f + expf(-v)); }

#define FMA2(acc, w, h) \
    asm("fma.rn.f32x2 %0, %1, %2, %0;" : "+l"(acc) : "l"(w), "l"(h))

__device__ __forceinline__ float packsum(unsigned long long a,
                                         unsigned long long b) {
    return (__uint_as_float((unsigned)(a & 0xffffffffull))
          + __uint_as_float((unsigned)(a >> 32)))
         + (__uint_as_float((unsigned)(b & 0xffffffffull))
          + __uint_as_float((unsigned)(b >> 32)));
}

// Fused 3-row quarter-dot: rows (u, 64+u, 128+u), columns {8q+32c+j}.
// Joins quarters with shfl_xor(1) and shfl_xor(2). All lanes get full sums.
__device__ __forceinline__ void dot3q(const float* __restrict__ w0,
                                      const float* __restrict__ w1,
                                      const float* __restrict__ w2,
                                      const float* __restrict__ hbp,
                                      int qoff,
                                      float& s0, float& s1, float& s2) {
    unsigned long long A00 = 0, A01 = 0, A10 = 0, A11 = 0, A20 = 0, A21 = 0;
#pragma unroll
    for (int c = 0; c < 8; c++) {
        int off = qoff + 32 * c + (c >= 4 ? 4 : 0);
        ulonglong2 hA = *(const ulonglong2*)(hbp + off);
        ulonglong2 hB = *(const ulonglong2*)(hbp + off + 4);
        ulonglong2 wA0 = *(const ulonglong2*)(w0 + off);
        ulonglong2 wB0 = *(const ulonglong2*)(w0 + off + 4);
        FMA2(A00, wA0.x, hA.x); FMA2(A01, wA0.y, hA.y);
        FMA2(A00, wB0.x, hB.x); FMA2(A01, wB0.y, hB.y);
        ulonglong2 wA1 = *(const ulonglong2*)(w1 + off);
        ulonglong2 wB1 = *(const ulonglong2*)(w1 + off + 4);
        FMA2(A10, wA1.x, hA.x); FMA2(A11, wA1.y, hA.y);
        FMA2(A10, wB1.x, hB.x); FMA2(A11, wB1.y, hB.y);
        ulonglong2 wA2 = *(const ulonglong2*)(w2 + off);
        ulonglong2 wB2 = *(const ulonglong2*)(w2 + off + 4);
        FMA2(A20, wA2.x, hA.x); FMA2(A21, wA2.y, hA.y);
        FMA2(A20, wB2.x, hB.x); FMA2(A21, wB2.y, hB.y);
    }
    s0 = packsum(A00, A01);
    s1 = packsum(A10, A11);
    s2 = packsum(A20, A21);
    s0 += __shfl_xor_sync(0xffffffffu, s0, 1);
    s0 += __shfl_xor_sync(0xffffffffu, s0, 2);
    s1 += __shfl_xor_sync(0xffffffffu, s1, 1);
    s1 += __shfl_xor_sync(0xffffffffu, s1, 2);
    s2 += __shfl_xor_sync(0xffffffffu, s2, 1);
    s2 += __shfl_xor_sync(0xffffffffu, s2, 2);
}

// ---------------- Pre-kernel: gi[t][b][o] = b_ih_e[o] + x[b,t,:] . W_ih_e[o,:] ----
__global__ void __launch_bounds__(256, 1)
gi_kernel(const float* __restrict__ x,
          const float* __restrict__ Wihe,
          const float* __restrict__ bihe)
{
    __shared__ float xs[64 * Pdim];
    const int t = blockIdx.x;
    const int o = blockIdx.y * 256 + threadIdx.x;

    float4 wr[16];
    const float4* Wr = (const float4*)(Wihe + o * Pdim);
#pragma unroll
    for (int k = 0; k < 16; k++) wr[k] = Wr[k];
    const float bia = bihe[o];

    for (int idx = threadIdx.x; idx < 64 * Pdim; idx += 256) {
        int b = idx >> 6, p = idx & 63;
        xs[idx] = x[((size_t)b * Lseq + t) * Pdim + p];
    }
    __syncthreads();

    for (int b = 0; b < 64; b++) {
        const float4* xr = (const float4*)(xs + b * Pdim);
        float a0 = bia, a1 = 0.f, a2 = 0.f, a3 = 0.f;
#pragma unroll
        for (int k = 0; k < 16; k++) {
            float4 w = wr[k], xx = xr[k];
            a0 = fmaf(w.x, xx.x, a0); a1 = fmaf(w.y, xx.y, a1);
            a2 = fmaf(w.z, xx.z, a2); a3 = fmaf(w.w, xx.w, a3);
        }
        g_gi[((size_t)t * 64 + b) * GI3H + o] = (a0 + a1) + (a2 + a3);
    }
}

// ---------------- Main recurrent kernel ----------------
__global__ void __cluster_dims__(CLUSTER, 1, 1) __launch_bounds__(NTHREADS, 1)
attn_net_kernel(const float* __restrict__ x,
                const float* __restrict__ Wihe, const float* __restrict__ Whhe,
                const float* __restrict__ bihe, const float* __restrict__ bhhe,
                const float* __restrict__ Wihd, const float* __restrict__ Whhd,
                const float* __restrict__ bihd, const float* __restrict__ bhhd,
                const float* __restrict__ Wdec, const float* __restrict__ bdec_p,
                const float* __restrict__ Wattn, const float* __restrict__ battn,
                const float* __restrict__ Wout, const float* __restrict__ bout,
                float* __restrict__ out)
{
    extern __shared__ char smem_raw[];
    Smem& S = *reinterpret_cast<Smem*>(smem_raw);

    const int tid = threadIdx.x;
    uint32_t rank;
    asm("mov.u32 %0, %%cluster_ctarank;" : "=r"(rank));
    const int g    = blockIdx.x >> 2;            // cluster id 0..31
    const int b0   = g * B_TILE;
    const int U0   = (int)rank * UNITSL;
    const int U0pad = U0 + (U0 >= 128 ? 4 : 0);
    const int u    = tid >> 3;                   // unit 0..63
    const int bb   = (tid >> 2) & 1;             // batch 0/1
    const int q    = tid & 3;                    // quarter 0..3
    const int qoff = q * 8;
    const bool storer = (q == 0) && ((u & 3) == 0);

    const float* w0 = &S.Wh[(u      ) * WH_PAD];
    const float* w1 = &S.Wh[(64 + u ) * WH_PAD];
    const float* w2 = &S.Wh[(128 + u) * WH_PAD];

    // ---------------- Phase 0: encoder recurrent weights ----------------
    for (int idx = tid; idx < ROWSL * Hdim; idx += NTHREADS) {
        int lr = idx >> 8, k = idx & 255;
        int grow = (lr >> 6) * Hdim + U0 + (lr & 63);
        S.Wh[lr * WH_PAD + k + (k >= 128 ? 4 : 0)] = Whhe[grow * Hdim + k];
    }
    for (int idx = tid; idx < Hdim; idx += NTHREADS) {
        S.wa[idx]   = Wattn[Hdim + idx];
        S.wdec[idx] = Wdec[idx];
    }
    for (int idx = tid; idx < 2 * B_TILE * HB_PAD; idx += NTHREADS)
        ((float*)S.hb)[idx] = 0.f;

    // recurrent biases -> registers
    float bg0 = bhhe[U0 + u];
    float bg1 = bhhe[Hdim + U0 + u];
    float bg2 = bhhe[2 * Hdim + U0 + u];
    __syncthreads();
    csync();

    // Remote DSMEM addresses for the packed h broadcast (store lanes only)
    uint32_t raddr[2][CLUSTER];
    if (storer) {
#pragma unroll
        for (int buf = 0; buf < 2; buf++) {
            uint32_t la = s2u(&S.hb[buf][bb][U0pad + u]);
#pragma unroll
            for (int pr = 0; pr < CLUSTER; pr++)
                raddr[buf][pr] = mapa_r(la, pr);
        }
    }

    // gi prefetch (one step ahead), hidden value carried in register
    const float* giP = g_gi + (size_t)(b0 + bb) * GI3H + U0 + u;
    float g0 = giP[0], g1 = giP[256], g2 = giP[512];
    float hprev = 0.f;

    // Warps 0-1 = batches 0-1: online-softmax state
    float m_run = -3.0e38f, Z_run = 0.f, C0 = 0.f, C1 = 0.f;

    // ---------------- Phase 1: encoder GRU + online-softmax attention ----------------
    for (int t = 0; t < Lseq; t++) {
        const int cur = t & 1, nxt = cur ^ 1;

        float n0 = 0.f, n1 = 0.f, n2 = 0.f;
        if ((t + 1) < Lseq) {
            const float* p = giP + (size_t)(t + 1) * (64 * GI3H);
            n0 = p[0]; n1 = p[256]; n2 = p[512];
        }

        float s0, s1, s2;
        dot3q(w0, w1, w2, &S.hb[cur][bb][0], qoff, s0, s1, s2);

        float r  = sigf(g0 + bg0 + s0);
        float z  = sigf(g1 + bg1 + s1);
        float nn = tanhf(g2 + r * (bg2 + s2));
        float hn = (1.f - z) * nn + z * hprev;
        hprev = hn;
        g0 = n0; g1 = n1; g2 = n2;

        // pack 4 units, broadcast to all 4 CTAs
        float v1 = __shfl_down_sync(0xffffffffu, hn, 8);
        float v2 = __shfl_down_sync(0xffffffffu, hn, 16);
        float v3 = __shfl_down_sync(0xffffffffu, hn, 24);
        if (storer) {
#pragma unroll
            for (int pr = 0; pr < CLUSTER; pr++) {
                st_clu64(raddr[nxt][pr],     hn, v1);
                st_clu64(raddr[nxt][pr] + 8, v2, v3);
            }
        }
        csync();

        // warp w owns batch w: h_proj + online softmax + context (overlaps next GEMV)
        if (tid < 64) {
            int w = tid >> 5, l = tid & 31;
            const float* hr = S.hb[nxt][w];
            float p = 0.f;
#pragma unroll
            for (int j = l; j < 128; j += 32) p += hr[j] * S.wa[j];
#pragma unroll
            for (int j = 128 + l; j < 256; j += 32) p += hr[j + 4] * S.wa[j];
#pragma unroll
            for (int o = 16; o > 0; o >>= 1) p += __shfl_xor_sync(0xffffffffu, p, o);
            float mn  = fmaxf(m_run, p);
            float sc  = expf(m_run - mn);
            float wgt = expf(p - mn);
            Z_run = Z_run * sc + wgt;
            m_run = mn;
            C0 = C0 * sc + wgt * hr[U0pad + l];
            C1 = C1 * sc + wgt * hr[U0pad + 32 + l];
        }
    }
    // final hidden state h(1024) in hb[0]; hprev register = s0

    // ---------------- Phase 1.5: context c -> hb[1] everywhere ----------------
    __syncthreads();
    if (tid < 64) {
        int w = tid >> 5, l = tid & 31;
        float iz = 1.f / Z_run;
        S.red[w * 64 + l]      = C0 * iz;
        S.red[w * 64 + 32 + l] = C1 * iz;
    }
    __syncthreads();
    if (storer) {
        float c0 = S.red[bb * 64 + u],     c1 = S.red[bb * 64 + u + 1];
        float c2 = S.red[bb * 64 + u + 2], c3 = S.red[bb * 64 + u + 3];
#pragma unroll
        for (int pr = 0; pr < CLUSTER; pr++) {
            st_clu64(raddr[1][pr],     c0, c1);
            st_clu64(raddr[1][pr] + 8, c2, c3);
        }
    }
    csync();

    // decoder input weights; giD = W_ih_d . c + b_ih_d  (into registers)
    for (int idx = tid; idx < ROWSL * Hdim; idx += NTHREADS) {
        int lr = idx >> 8, k = idx & 255;
        int grow = (lr >> 6) * Hdim + U0 + (lr & 63);
        S.Wh[lr * WH_PAD + k + (k >= 128 ? 4 : 0)] = Wihd[grow * Hdim + k];
    }
    __syncthreads();
    float gid0, gid1, gid2;
    {
        float s0, s1, s2;
        dot3q(w0, w1, w2, &S.hb[1][bb][0], qoff, s0, s1, s2);
        gid0 = bihd[U0 + u] + s0;
        gid1 = bihd[Hdim + U0 + u] + s1;
        gid2 = bihd[2 * Hdim + U0 + u] + s2;
    }
    __syncthreads();

    // decoder recurrent weights + biases
    for (int idx = tid; idx < ROWSL * Hdim; idx += NTHREADS) {
        int lr = idx >> 8, k = idx & 255;
        int grow = (lr >> 6) * Hdim + U0 + (lr & 63);
        S.Wh[lr * WH_PAD + k + (k >= 128 ? 4 : 0)] = Whhd[grow * Hdim + k];
    }
    bg0 = bhhd[U0 + u];
    bg1 = bhhd[Hdim + U0 + u];
    bg2 = bhhd[2 * Hdim + U0 + u];
    const float bdec = bdec_p[0];
    __syncthreads();
    csync();

    // ---------------- Phase 2: decoder GRU (constant input gates) ----------------
    for (int i = 0; i < Lseq; i++) {
        const int cur = i & 1, nxt = cur ^ 1;

        float s0, s1, s2;
        dot3q(w0, w1, w2, &S.hb[cur][bb][0], qoff, s0, s1, s2);

        float r  = sigf(gid0 + bg0 + s0);
        float z  = sigf(gid1 + bg1 + s1);
        float nn = tanhf(gid2 + r * (bg2 + s2));
        float sn = (1.f - z) * nn + z * hprev;
        hprev = sn;

        float v1 = __shfl_down_sync(0xffffffffu, sn, 8);
        float v2 = __shfl_down_sync(0xffffffffu, sn, 16);
        float v3 = __shfl_down_sync(0xffffffffu, sn, 24);
        if (storer) {
#pragma unroll
            for (int pr = 0; pr < CLUSTER; pr++) {
                st_clu64(raddr[nxt][pr],     sn, v1);
                st_clu64(raddr[nxt][pr] + 8, v2, v3);
            }
        }
        csync();

        // y_i[b] = sigmoid(s_new . w_dec + b_dec); overlaps next step's GEMV
        if (tid < 64) {
            int w = tid >> 5, l = tid & 31;
            const float* hr = S.hb[nxt][w];
            float p = 0.f;
#pragma unroll
            for (int j = l; j < 128; j += 32) p += hr[j] * S.wdec[j];
#pragma unroll
            for (int j = 128 + l; j < 256; j += 32) p += hr[j + 4] * S.wdec[j];
#pragma unroll
            for (int o = 16; o > 0; o >>= 1) p += __shfl_xor_sync(0xffffffffu, p, o);
            if (l == 0) S.yb[i * 2 + w] = sigf(p + bdec);
        }
    }

    // ---------------- Phase 3: out = y @ W_out^T + b_out ----------------
    __syncthreads();
    {
        int part = tid >> 6;                // 0..7
        int ob   = tid & 63;                // 32 o-rows x 2 batches
        int o    = (int)rank * 32 + (ob >> 1);
        int b    = ob & 1;
        float acc = 0.f;
        for (int i = part; i < Lseq; i += PARTS)
            acc += S.yb[i * 2 + b] * Wout[o * Lseq + i];
        S.red[ob * PARTS + part] = acc;
    }
    __syncthreads();
    if (tid < 64) {
        int o = (int)rank * 32 + (tid >> 1);
        int b = tid & 1;
        float s = bout[o];
#pragma unroll
        for (int p8 = 0; p8 < PARTS; p8++) s += S.red[tid * PARTS + p8];
        out[(b0 + b) * OUTD + o] = s;
    }
}

extern "C" void kernel_launch(void* const* d_in, const int* in_sizes, int n_in,
                              void* d_out, int out_size) {
    (void)in_sizes; (void)n_in; (void)out_size;

    // Pre-kernel: gi = x @ W_ih_e^T + b_ih_e for all timesteps
    gi_kernel<<<dim3(Lseq, 3), 256>>>(
        (const float*)d_in[0], (const float*)d_in[1], (const float*)d_in[3]);

    cudaFuncSetAttribute(attn_net_kernel,
                         cudaFuncAttributeMaxDynamicSharedMemorySize,
                         (int)sizeof(Smem));
    attn_net_kernel<<<128, NTHREADS, sizeof(Smem)>>>(
        (const float*)d_in[0],  (const float*)d_in[1],  (const float*)d_in[2],
        (const float*)d_in[3],  (const float*)d_in[4],  (const float*)d_in[5],
        (const float*)d_in[6],  (const float*)d_in[7],  (const float*)d_in[8],
        (const float*)d_in[9],  (const float*)d_in[10], (const float*)d_in[11],
        (const float*)d_in[12], (const float*)d_in[13], (const float*)d_in[14],
        (float*)d_out);
}

// round 14
// speedup vs baseline: 2.8363x; 1.2755x over previous
#include <cuda_runtime.h>
#include <cstdint>

// Problem dims
#define Lseq  1024
#define Pdim  64
#define Hdim  256
#define OUTD  128
#define GI3H  768      // 3*Hdim

// 32 clusters x 4 CTAs. Cluster: 2 batch rows. CTA: 64 hidden units (192 gate rows).
// 512 threads: tid = u*8 + o. Thread computes gate rows (u, 64+u, 128+u) over its
// 32-column octant for BOTH batches (weights read once). Octants joined by shfl;
// batch folded with one shfl_xor(4): lanes o<4 own batch0, o>=4 own batch1.
#define CLUSTER  4
#define B_TILE   2
#define NTHREADS 512
#define UNITSL   64
#define ROWSL    192
#define WH_PAD   260       // 256 cols contiguous + 4 end-pad (row stride mod 32 = 4)
#define HB_PAD   268       // 256 cols contiguous + 12 end-pad
#define PARTS    8

// Precomputed encoder input gates: gi[t*64 + b][grow], grow = gate*256 + U0 + u
__device__ float g_gi[(size_t)Lseq * 64 * GI3H];   // 201 MB scratch

struct __align__(16) Smem {
    float Wh[ROWSL * WH_PAD];       // 192x256 weight slice (enc Whh -> dec Wih -> dec Whh)
    float hb[2][B_TILE][HB_PAD];    // double-buffered hidden state (contiguous cols)
    float wa[Hdim];                 // attention hidden weight row
    float wdec[Hdim];               // decoder output weight
    float yb[Lseq * B_TILE];        // decoder outputs
    float red[768];                 // staging: context / final GEMM reduction
};

__device__ __forceinline__ uint32_t s2u(const void* p) {
    uint32_t a;
    asm("{ .reg .u64 t; cvta.to.shared.u64 t, %1; cvt.u32.u64 %0, t; }"
        : "=r"(a) : "l"(p));
    return a;
}

__device__ __forceinline__ uint32_t mapa_r(uint32_t la, int r) {
    uint32_t ra;
    asm("mapa.shared::cluster.u32 %0, %1, %2;" : "=r"(ra) : "r"(la), "r"(r));
    return ra;
}

__device__ __forceinline__ void st_clu64(uint32_t ra, float a, float b) {
    unsigned long long v;
    asm("mov.b64 %0, {%1, %2};" : "=l"(v)
        : "r"(__float_as_uint(a)), "r"(__float_as_uint(b)));
    asm volatile("st.shared::cluster.b64 [%0], %1;" :: "r"(ra), "l"(v) : "memory");
}

__device__ __forceinline__ void csync() {
    asm volatile("barrier.cluster.arrive.aligned;" ::: "memory");
    asm volatile("barrier.cluster.wait.aligned;" ::: "memory");
}

__device__ __forceinline__ float sigf(float v) { return 1.0f / (1.0f + expf(-v)); }

#define FMA2(acc, w, h) \
    asm("fma.rn.f32x2 %0, %1, %2, %0;" : "+l"(acc) : "l"(w), "l"(h))

__device__ __forceinline__ float ps(unsigned long long a) {
    return __uint_as_float((unsigned)(a & 0xffffffffull))
         + __uint_as_float((unsigned)(a >> 32));
}

// Fused 3-row, 2-batch octant dot with bank rotation; full reduce + batch fold.
// Returns the 3 gate sums for the thread's primary batch (o>>2).
__device__ __forceinline__ void dot3b(const float* __restrict__ wp0,
                                      const float* __restrict__ wp1,
                                      const float* __restrict__ wp2,
                                      const float* __restrict__ h0,
                                      const float* __restrict__ h1,
                                      int o,
                                      float& s0, float& s1, float& s2) {
    unsigned long long A00=0, A01=0, A10=0, A11=0, A20=0, A21=0;
#pragma unroll
    for (int c = 0; c < 8; c++) {
        int off = 4 * ((o + c) & 7);            // bank-rotated chunk within octant
        ulonglong2 ha = *(const ulonglong2*)(h0 + off);
        ulonglong2 hc = *(const ulonglong2*)(h1 + off);
        ulonglong2 w  = *(const ulonglong2*)(wp0 + off);
        FMA2(A00, w.x, ha.x);  FMA2(A00, w.y, ha.y);
        FMA2(A01, w.x, hc.x);  FMA2(A01, w.y, hc.y);
        w = *(const ulonglong2*)(wp1 + off);
        FMA2(A10, w.x, ha.x);  FMA2(A10, w.y, ha.y);
        FMA2(A11, w.x, hc.x);  FMA2(A11, w.y, hc.y);
        w = *(const ulonglong2*)(wp2 + off);
        FMA2(A20, w.x, ha.x);  FMA2(A20, w.y, ha.y);
        FMA2(A21, w.x, hc.x);  FMA2(A21, w.y, hc.y);
    }
    float p00 = ps(A00), p01 = ps(A01);
    float p10 = ps(A10), p11 = ps(A11);
    float p20 = ps(A20), p21 = ps(A21);
    const bool lo = (o < 4);
    float t0 = lo ? p01 : p00;
    float t1 = lo ? p11 : p10;
    float t2 = lo ? p21 : p20;
    t0 = __shfl_xor_sync(0xffffffffu, t0, 4);
    t1 = __shfl_xor_sync(0xffffffffu, t1, 4);
    t2 = __shfl_xor_sync(0xffffffffu, t2, 4);
    s0 = (lo ? p00 : p01) + t0;
    s1 = (lo ? p10 : p11) + t1;
    s2 = (lo ? p20 : p21) + t2;
    s0 += __shfl_xor_sync(0xffffffffu, s0, 1);
    s0 += __shfl_xor_sync(0xffffffffu, s0, 2);
    s1 += __shfl_xor_sync(0xffffffffu, s1, 1);
    s1 += __shfl_xor_sync(0xffffffffu, s1, 2);
    s2 += __shfl_xor_sync(0xffffffffu, s2, 1);
    s2 += __shfl_xor_sync(0xffffffffu, s2, 2);
}

// ---------------- Pre-kernel: gi[t][b][o] = b_ih_e[o] + x[b,t,:] . W_ih_e[o,:] ----
__global__ void __launch_bounds__(256, 1)
gi_kernel(const float* __restrict__ x,
          const float* __restrict__ Wihe,
          const float* __restrict__ bihe)
{
    __shared__ float xs[64 * Pdim];
    const int t = blockIdx.x;
    const int o = blockIdx.y * 256 + threadIdx.x;

    float4 wr[16];
    const float4* Wr = (const float4*)(Wihe + o * Pdim);
#pragma unroll
    for (int k = 0; k < 16; k++) wr[k] = Wr[k];
    const float bia = bihe[o];

    for (int idx = threadIdx.x; idx < 64 * Pdim; idx += 256) {
        int b = idx >> 6, p = idx & 63;
        xs[idx] = x[((size_t)b * Lseq + t) * Pdim + p];
    }
    __syncthreads();

    for (int b = 0; b < 64; b++) {
        const float4* xr = (const float4*)(xs + b * Pdim);
        float a0 = bia, a1 = 0.f, a2 = 0.f, a3 = 0.f;
#pragma unroll
        for (int k = 0; k < 16; k++) {
            float4 w = wr[k], xx = xr[k];
            a0 = fmaf(w.x, xx.x, a0); a1 = fmaf(w.y, xx.y, a1);
            a2 = fmaf(w.z, xx.z, a2); a3 = fmaf(w.w, xx.w, a3);
        }
        g_gi[((size_t)t * 64 + b) * GI3H + o] = (a0 + a1) + (a2 + a3);
    }
}

// ---------------- Main recurrent kernel ----------------
__global__ void __cluster_dims__(CLUSTER, 1, 1) __launch_bounds__(NTHREADS, 1)
attn_net_kernel(const float* __restrict__ x,
                const float* __restrict__ Wihe, const float* __restrict__ Whhe,
                const float* __restrict__ bihe, const float* __restrict__ bhhe,
                const float* __restrict__ Wihd, const float* __restrict__ Whhd,
                const float* __restrict__ bihd, const float* __restrict__ bhhd,
                const float* __restrict__ Wdec, const float* __restrict__ bdec_p,
                const float* __restrict__ Wattn, const float* __restrict__ battn,
                const float* __restrict__ Wout, const float* __restrict__ bout,
                float* __restrict__ out)
{
    extern __shared__ char smem_raw[];
    Smem& S = *reinterpret_cast<Smem*>(smem_raw);

    const int tid = threadIdx.x;
    uint32_t rank;
    asm("mov.u32 %0, %%cluster_ctarank;" : "=r"(rank));
    const int g   = blockIdx.x >> 2;             // cluster id 0..31
    const int b0  = g * B_TILE;
    const int U0  = (int)rank * UNITSL;
    const int u   = tid >> 3;                    // unit 0..63
    const int o   = tid & 7;                     // octant 0..7
    const int pb  = o >> 2;                      // primary batch 0/1
    const bool storer = ((o & 3) == 0) && ((u & 3) == 0);  // o in {0,4}, u%4==0

    const float* wp0 = &S.Wh[u * WH_PAD + o * 32];
    const float* wp1 = wp0 + 64 * WH_PAD;
    const float* wp2 = wp0 + 128 * WH_PAD;
    const int hoff = o * 32;

    // ---------------- Phase 0: encoder recurrent weights ----------------
    for (int idx = tid; idx < ROWSL * Hdim; idx += NTHREADS) {
        int lr = idx >> 8, k = idx & 255;
        int grow = (lr >> 6) * Hdim + U0 + (lr & 63);
        S.Wh[lr * WH_PAD + k] = Whhe[grow * Hdim + k];
    }
    for (int idx = tid; idx < Hdim; idx += NTHREADS) {
        S.wa[idx]   = Wattn[Hdim + idx];
        S.wdec[idx] = Wdec[idx];
    }
    for (int idx = tid; idx < 2 * B_TILE * HB_PAD; idx += NTHREADS)
        ((float*)S.hb)[idx] = 0.f;

    float bg0 = bhhe[U0 + u];
    float bg1 = bhhe[Hdim + U0 + u];
    float bg2 = bhhe[2 * Hdim + U0 + u];
    __syncthreads();
    csync();

    // Remote DSMEM addresses for packed h broadcast (store lanes only)
    uint32_t raddr[2][CLUSTER];
    if (storer) {
#pragma unroll
        for (int buf = 0; buf < 2; buf++) {
            uint32_t la = s2u(&S.hb[buf][pb][U0 + u]);
#pragma unroll
            for (int pr = 0; pr < CLUSTER; pr++)
                raddr[buf][pr] = mapa_r(la, pr);
        }
    }

    // gi prefetch for primary batch (one step ahead); h carried in register
    const float* giP = g_gi + (size_t)(b0 + pb) * GI3H + U0 + u;
    float g0 = giP[0], g1 = giP[256], g2 = giP[512];
    float hprev = 0.f;

    // Warps 0-1 = batches 0-1: online-softmax state
    float m_run = -3.0e38f, Z_run = 0.f, C0 = 0.f, C1 = 0.f;

    // ---------------- Phase 1: encoder GRU + online-softmax attention ----------------
    for (int t = 0; t < Lseq; t++) {
        const int cur = t & 1, nxt = cur ^ 1;

        float n0 = 0.f, n1 = 0.f, n2 = 0.f;
        if ((t + 1) < Lseq) {
            const float* p = giP + (size_t)(t + 1) * (64 * GI3H);
            n0 = p[0]; n1 = p[256]; n2 = p[512];
        }

        float s0, s1, s2;
        dot3b(wp0, wp1, wp2,
              &S.hb[cur][0][hoff], &S.hb[cur][1][hoff], o, s0, s1, s2);

        float r  = sigf(g0 + bg0 + s0);
        float z  = sigf(g1 + bg1 + s1);
        float nn = tanhf(g2 + r * (bg2 + s2));
        float hn = (1.f - z) * nn + z * hprev;
        hprev = hn;
        g0 = n0; g1 = n1; g2 = n2;

        // pack 4 units (same o), broadcast to all 4 CTAs
        float v1 = __shfl_down_sync(0xffffffffu, hn, 8);
        float v2 = __shfl_down_sync(0xffffffffu, hn, 16);
        float v3 = __shfl_down_sync(0xffffffffu, hn, 24);
        if (storer) {
#pragma unroll
            for (int pr = 0; pr < CLUSTER; pr++) {
                st_clu64(raddr[nxt][pr],     hn, v1);
                st_clu64(raddr[nxt][pr] + 8, v2, v3);
            }
        }
        csync();

        // warp w owns batch w: h_proj + online softmax + context (overlaps next GEMV)
        if (tid < 64) {
            int w = tid >> 5, l = tid & 31;
            const float* hr = S.hb[nxt][w];
            float p = 0.f;
#pragma unroll
            for (int j = l; j < 256; j += 32) p += hr[j] * S.wa[j];
#pragma unroll
            for (int ofs = 16; ofs > 0; ofs >>= 1) p += __shfl_xor_sync(0xffffffffu, p, ofs);
            float mn  = fmaxf(m_run, p);
            float sc  = expf(m_run - mn);
            float wgt = expf(p - mn);
            Z_run = Z_run * sc + wgt;
            m_run = mn;
            C0 = C0 * sc + wgt * hr[U0 + l];
            C1 = C1 * sc + wgt * hr[U0 + 32 + l];
        }
    }
    // h_T in hb[0]; hprev register = h_T (primary batch)

    // ---------------- Phase 1.5: context c -> hb[1] everywhere ----------------
    __syncthreads();
    if (tid < 64) {
        int w = tid >> 5, l = tid & 31;
        float iz = 1.f / Z_run;
        S.red[w * 64 + l]      = C0 * iz;
        S.red[w * 64 + 32 + l] = C1 * iz;
    }
    __syncthreads();
    if (storer) {
        float c0 = S.red[pb * 64 + u],     c1 = S.red[pb * 64 + u + 1];
        float c2 = S.red[pb * 64 + u + 2], c3 = S.red[pb * 64 + u + 3];
#pragma unroll
        for (int pr = 0; pr < CLUSTER; pr++) {
            st_clu64(raddr[1][pr],     c0, c1);
            st_clu64(raddr[1][pr] + 8, c2, c3);
        }
    }
    csync();

    // decoder input weights; giD = W_ih_d . c + b_ih_d (registers, primary batch)
    for (int idx = tid; idx < ROWSL * Hdim; idx += NTHREADS) {
        int lr = idx >> 8, k = idx & 255;
        int grow = (lr >> 6) * Hdim + U0 + (lr & 63);
        S.Wh[lr * WH_PAD + k] = Wihd[grow * Hdim + k];
    }
    __syncthreads();
    float gid0, gid1, gid2;
    {
        float s0, s1, s2;
        dot3b(wp0, wp1, wp2,
              &S.hb[1][0][hoff], &S.hb[1][1][hoff], o, s0, s1, s2);
        gid0 = bihd[U0 + u] + s0;
        gid1 = bihd[Hdim + U0 + u] + s1;
        gid2 = bihd[2 * Hdim + U0 + u] + s2;
    }
    __syncthreads();

    // decoder recurrent weights + biases
    for (int idx = tid; idx < ROWSL * Hdim; idx += NTHREADS) {
        int lr = idx >> 8, k = idx & 255;
        int grow = (lr >> 6) * Hdim + U0 + (lr & 63);
        S.Wh[lr * WH_PAD + k] = Whhd[grow * Hdim + k];
    }
    bg0 = bhhd[U0 + u];
    bg1 = bhhd[Hdim + U0 + u];
    bg2 = bhhd[2 * Hdim + U0 + u];
    const float bdec = bdec_p[0];
    __syncthreads();
    csync();

    // ---------------- Phase 2: decoder GRU (constant input gates) ----------------
    for (int i = 0; i < Lseq; i++) {
        const int cur = i & 1, nxt = cur ^ 1;

        float s0, s1, s2;
        dot3b(wp0, wp1, wp2,
              &S.hb[cur][0][hoff], &S.hb[cur][1][hoff], o, s0, s1, s2);

        float r  = sigf(gid0 + bg0 + s0);
        float z  = sigf(gid1 + bg1 + s1);
        float nn = tanhf(gid2 + r * (bg2 + s2));
        float sn = (1.f - z) * nn + z * hprev;
        hprev = sn;

        float v1 = __shfl_down_sync(0xffffffffu, sn, 8);
        float v2 = __shfl_down_sync(0xffffffffu, sn, 16);
        float v3 = __shfl_down_sync(0xffffffffu, sn, 24);
        if (storer) {
#pragma unroll
            for (int pr = 0; pr < CLUSTER; pr++) {
                st_clu64(raddr[nxt][pr],     sn, v1);
                st_clu64(raddr[nxt][pr] + 8, v2, v3);
            }
        }
        csync();

        // y_i[b] = sigmoid(s_new . w_dec + b_dec); overlaps next step's GEMV
        if (tid < 64) {
            int w = tid >> 5, l = tid & 31;
            const float* hr = S.hb[nxt][w];
            float p = 0.f;
#pragma unroll
            for (int j = l; j < 256; j += 32) p += hr[j] * S.wdec[j];
#pragma unroll
            for (int ofs = 16; ofs > 0; ofs >>= 1) p += __shfl_xor_sync(0xffffffffu, p, ofs);
            if (l == 0) S.yb[i * 2 + w] = sigf(p + bdec);
        }
    }

    // ---------------- Phase 3: out = y @ W_out^T + b_out ----------------
    __syncthreads();
    {
        int part = tid >> 6;                // 0..7
        int ob   = tid & 63;                // 32 o-rows x 2 batches
        int orow = (int)rank * 32 + (ob >> 1);
        int b    = ob & 1;
        float acc = 0.f;
        for (int i = part; i < Lseq; i += PARTS)
            acc += S.yb[i * 2 + b] * Wout[orow * Lseq + i];
        S.red[ob * PARTS + part] = acc;
    }
    __syncthreads();
    if (tid < 64) {
        int orow = (int)rank * 32 + (tid >> 1);
        int b    = tid & 1;
        float s  = bout[orow];
#pragma unroll
        for (int p8 = 0; p8 < PARTS; p8++) s += S.red[tid * PARTS + p8];
        out[(b0 + b) * OUTD + orow] = s;
    }
}

extern "C" void kernel_launch(void* const* d_in, const int* in_sizes, int n_in,
                              void* d_out, int out_size) {
    (void)in_sizes; (void)n_in; (void)out_size;

    // Pre-kernel: gi = x @ W_ih_e^T + b_ih_e for all timesteps
    gi_kernel<<<dim3(Lseq, 3), 256>>>(
        (const float*)d_in[0], (const float*)d_in[1], (const float*)d_in[3]);

    cudaFuncSetAttribute(attn_net_kernel,
                         cudaFuncAttributeMaxDynamicSharedMemorySize,
                         (int)sizeof(Smem));
    attn_net_kernel<<<128, NTHREADS, sizeof(Smem)>>>(
        (const float*)d_in[0],  (const float*)d_in[1],  (const float*)d_in[2],
        (const float*)d_in[3],  (const float*)d_in[4],  (const float*)d_in[5],
        (const float*)d_in[6],  (const float*)d_in[7],  (const float*)d_in[8],
        (const float*)d_in[9],  (const float*)d_in[10], (const float*)d_in[11],
        (const float*)d_in[12], (const float*)d_in[13], (const float*)d_in[14],
        (float*)d_out);
}

// round 15
// speedup vs baseline: 3.1424x; 1.1079x over previous
#include <cuda_runtime.h>
#include <cstdint>

// Problem dims
#define Lseq  1024
#define Pdim  64
#define Hdim  256
#define OUTD  128
#define GI3H  768      // 3*Hdim

// 32 clusters x 4 CTAs. Cluster: 2 batch rows. CTA: 64 hidden units (192 gate rows).
// 512 threads: tid = u*8 + o. Thread computes gate rows (u, 64+u, 128+u) over its
// 32-column octant for BOTH batches (weights read once). Octants joined by shfl;
// batch folded with one shfl_xor(4): lanes o<4 own batch0, o>=4 own batch1.
// Triple-buffered h + split cluster arrive/wait: attention/y runs inside the
// barrier window on the PREVIOUS state (index-shifted, tail-corrected).
#define CLUSTER  4
#define B_TILE   2
#define NTHREADS 512
#define UNITSL   64
#define ROWSL    192
#define WH_PAD   260       // 256 cols contiguous + 4 end-pad (row stride mod 32 = 4)
#define HB_PAD   268       // 256 cols contiguous + 12 end-pad
#define NBUF     3
#define HBYTES   (B_TILE * HB_PAD * 4)   // byte stride between h buffers
#define PARTS    8

// Precomputed encoder input gates: gi[t*64 + b][grow], grow = gate*256 + U0 + u
__device__ float g_gi[(size_t)Lseq * 64 * GI3H];   // 201 MB scratch

struct __align__(16) Smem {
    float Wh[ROWSL * WH_PAD];        // 192x256 weight slice (enc Whh -> dec Wih -> dec Whh)
    float hb[NBUF][B_TILE][HB_PAD];  // triple-buffered hidden state
    float wa[Hdim];                  // attention hidden weight row
    float wdec[Hdim];                // decoder output weight
    float yb[Lseq * B_TILE];         // decoder outputs
    float red[768];                  // staging: context / final GEMM reduction
};

__device__ __forceinline__ uint32_t s2u(const void* p) {
    uint32_t a;
    asm("{ .reg .u64 t; cvta.to.shared.u64 t, %1; cvt.u32.u64 %0, t; }"
        : "=r"(a) : "l"(p));
    return a;
}

__device__ __forceinline__ uint32_t mapa_r(uint32_t la, int r) {
    uint32_t ra;
    asm("mapa.shared::cluster.u32 %0, %1, %2;" : "=r"(ra) : "r"(la), "r"(r));
    return ra;
}

__device__ __forceinline__ void st_clu64(uint32_t ra, float a, float b) {
    unsigned long long v;
    asm("mov.b64 %0, {%1, %2};" : "=l"(v)
        : "r"(__float_as_uint(a)), "r"(__float_as_uint(b)));
    asm volatile("st.shared::cluster.b64 [%0], %1;" :: "r"(ra), "l"(v) : "memory");
}

__device__ __forceinline__ void carrive() {
    asm volatile("barrier.cluster.arrive.aligned;" ::: "memory");
}
__device__ __forceinline__ void cwait() {
    asm volatile("barrier.cluster.wait.aligned;" ::: "memory");
}
__device__ __forceinline__ void csync() { carrive(); cwait(); }

// sigmoid via single MUFU.TANH
__device__ __forceinline__ float sigf(float v) {
    return 0.5f * tanhf(0.5f * v) + 0.5f;
}

#define FMA2(acc, w, h) \
    asm("fma.rn.f32x2 %0, %1, %2, %0;" : "+l"(acc) : "l"(w), "l"(h))

__device__ __forceinline__ float ps(unsigned long long a) {
    return __uint_as_float((unsigned)(a & 0xffffffffull))
         + __uint_as_float((unsigned)(a >> 32));
}

// Fused 3-row, 2-batch octant dot with bank rotation; full reduce + batch fold.
// Returns the 3 gate sums for the thread's primary batch (o>>2).
__device__ __forceinline__ void dot3b(const float* __restrict__ wp0,
                                      const float* __restrict__ wp1,
                                      const float* __restrict__ wp2,
                                      const float* __restrict__ h0,
                                      const float* __restrict__ h1,
                                      int o,
                                      float& s0, float& s1, float& s2) {
    unsigned long long A00=0, A01=0, A10=0, A11=0, A20=0, A21=0;
#pragma unroll
    for (int c = 0; c < 8; c++) {
        int off = 4 * ((o + c) & 7);            // bank-rotated chunk within octant
        ulonglong2 ha = *(const ulonglong2*)(h0 + off);
        ulonglong2 hc = *(const ulonglong2*)(h1 + off);
        ulonglong2 w  = *(const ulonglong2*)(wp0 + off);
        FMA2(A00, w.x, ha.x);  FMA2(A00, w.y, ha.y);
        FMA2(A01, w.x, hc.x);  FMA2(A01, w.y, hc.y);
        w = *(const ulonglong2*)(wp1 + off);
        FMA2(A10, w.x, ha.x);  FMA2(A10, w.y, ha.y);
        FMA2(A11, w.x, hc.x);  FMA2(A11, w.y, hc.y);
        w = *(const ulonglong2*)(wp2 + off);
        FMA2(A20, w.x, ha.x);  FMA2(A20, w.y, ha.y);
        FMA2(A21, w.x, hc.x);  FMA2(A21, w.y, hc.y);
    }
    float p00 = ps(A00), p01 = ps(A01);
    float p10 = ps(A10), p11 = ps(A11);
    float p20 = ps(A20), p21 = ps(A21);
    const bool lo = (o < 4);
    float t0 = lo ? p01 : p00;
    float t1 = lo ? p11 : p10;
    float t2 = lo ? p21 : p20;
    t0 = __shfl_xor_sync(0xffffffffu, t0, 4);
    t1 = __shfl_xor_sync(0xffffffffu, t1, 4);
    t2 = __shfl_xor_sync(0xffffffffu, t2, 4);
    s0 = (lo ? p00 : p01) + t0;
    s1 = (lo ? p10 : p11) + t1;
    s2 = (lo ? p20 : p21) + t2;
    s0 += __shfl_xor_sync(0xffffffffu, s0, 1);
    s0 += __shfl_xor_sync(0xffffffffu, s0, 2);
    s1 += __shfl_xor_sync(0xffffffffu, s1, 1);
    s1 += __shfl_xor_sync(0xffffffffu, s1, 2);
    s2 += __shfl_xor_sync(0xffffffffu, s2, 1);
    s2 += __shfl_xor_sync(0xffffffffu, s2, 2);
}

// ---------------- Pre-kernel: gi[t][b][o] = b_ih_e[o] + x[b,t,:] . W_ih_e[o,:] ----
__global__ void __launch_bounds__(256, 1)
gi_kernel(const float* __restrict__ x,
          const float* __restrict__ Wihe,
          const float* __restrict__ bihe)
{
    __shared__ float xs[64 * Pdim];
    const int t = blockIdx.x;
    const int o = blockIdx.y * 256 + threadIdx.x;

    float4 wr[16];
    const float4* Wr = (const float4*)(Wihe + o * Pdim);
#pragma unroll
    for (int k = 0; k < 16; k++) wr[k] = Wr[k];
    const float bia = bihe[o];

    for (int idx = threadIdx.x; idx < 64 * Pdim; idx += 256) {
        int b = idx >> 6, p = idx & 63;
        xs[idx] = x[((size_t)b * Lseq + t) * Pdim + p];
    }
    __syncthreads();

    for (int b = 0; b < 64; b++) {
        const float4* xr = (const float4*)(xs + b * Pdim);
        float a0 = bia, a1 = 0.f, a2 = 0.f, a3 = 0.f;
#pragma unroll
        for (int k = 0; k < 16; k++) {
            float4 w = wr[k], xx = xr[k];
            a0 = fmaf(w.x, xx.x, a0); a1 = fmaf(w.y, xx.y, a1);
            a2 = fmaf(w.z, xx.z, a2); a3 = fmaf(w.w, xx.w, a3);
        }
        g_gi[((size_t)t * 64 + b) * GI3H + o] = (a0 + a1) + (a2 + a3);
    }
}

// ---------------- Main recurrent kernel ----------------
__global__ void __cluster_dims__(CLUSTER, 1, 1) __launch_bounds__(NTHREADS, 1)
attn_net_kernel(const float* __restrict__ x,
                const float* __restrict__ Wihe, const float* __restrict__ Whhe,
                const float* __restrict__ bihe, const float* __restrict__ bhhe,
                const float* __restrict__ Wihd, const float* __restrict__ Whhd,
                const float* __restrict__ bihd, const float* __restrict__ bhhd,
                const float* __restrict__ Wdec, const float* __restrict__ bdec_p,
                const float* __restrict__ Wattn, const float* __restrict__ battn,
                const float* __restrict__ Wout, const float* __restrict__ bout,
                float* __restrict__ out)
{
    extern __shared__ char smem_raw[];
    Smem& S = *reinterpret_cast<Smem*>(smem_raw);

    const int tid = threadIdx.x;
    uint32_t rank;
    asm("mov.u32 %0, %%cluster_ctarank;" : "=r"(rank));
    const int g   = blockIdx.x >> 2;             // cluster id 0..31
    const int b0  = g * B_TILE;
    const int U0  = (int)rank * UNITSL;
    const int u   = tid >> 3;                    // unit 0..63
    const int o   = tid & 7;                     // octant 0..7
    const int pb  = o >> 2;                      // primary batch 0/1
    const bool storer = ((o & 3) == 0) && ((u & 3) == 0);  // o in {0,4}, u%4==0

    const float* wp0 = &S.Wh[u * WH_PAD + o * 32];
    const float* wp1 = wp0 + 64 * WH_PAD;
    const float* wp2 = wp0 + 128 * WH_PAD;
    const int hoff = o * 32;

    // ---------------- Phase 0: encoder recurrent weights ----------------
    for (int idx = tid; idx < ROWSL * Hdim; idx += NTHREADS) {
        int lr = idx >> 8, k = idx & 255;
        int grow = (lr >> 6) * Hdim + U0 + (lr & 63);
        S.Wh[lr * WH_PAD + k] = Whhe[grow * Hdim + k];
    }
    for (int idx = tid; idx < Hdim; idx += NTHREADS) {
        S.wa[idx]   = Wattn[Hdim + idx];
        S.wdec[idx] = Wdec[idx];
    }
    for (int idx = tid; idx < NBUF * B_TILE * HB_PAD; idx += NTHREADS)
        ((float*)S.hb)[idx] = 0.f;

    float bg0 = bhhe[U0 + u];
    float bg1 = bhhe[Hdim + U0 + u];
    float bg2 = bhhe[2 * Hdim + U0 + u];
    __syncthreads();
    csync();

    // Remote DSMEM base addresses (buffer 0) for packed h broadcast (store lanes)
    uint32_t rbase[CLUSTER];
    if (storer) {
        uint32_t la = s2u(&S.hb[0][pb][U0 + u]);
#pragma unroll
        for (int pr = 0; pr < CLUSTER; pr++)
            rbase[pr] = mapa_r(la, pr);
    }

    // gi prefetch for primary batch (one step ahead); h carried in register
    const float* giP = g_gi + (size_t)(b0 + pb) * GI3H + U0 + u;
    float g0 = giP[0], g1 = giP[256], g2 = giP[512];
    float hprev = 0.f;

    // Warps 0-1 = batches 0-1: online-softmax state
    float m_run = -3.0e38f, Z_run = 0.f, C0 = 0.f, C1 = 0.f;

    // ---------------- Phase 1: encoder GRU + delayed online-softmax attention ----
    int cur = 0;
    for (int t = 0; t < Lseq; t++) {
        int nxt = cur + 1; if (nxt == NBUF) nxt = 0;

        float n0 = 0.f, n1 = 0.f, n2 = 0.f;
        if ((t + 1) < Lseq) {
            const float* p = giP + (size_t)(t + 1) * (64 * GI3H);
            n0 = p[0]; n1 = p[256]; n2 = p[512];
        }

        float s0, s1, s2;
        dot3b(wp0, wp1, wp2,
              &S.hb[cur][0][hoff], &S.hb[cur][1][hoff], o, s0, s1, s2);

        float r  = sigf(g0 + bg0 + s0);
        float z  = sigf(g1 + bg1 + s1);
        float nn = tanhf(g2 + r * (bg2 + s2));
        float hn = nn + z * (hprev - nn);
        hprev = hn;
        g0 = n0; g1 = n1; g2 = n2;

        // pack 4 units (same o), broadcast to all 4 CTAs into buffer nxt
        float v1 = __shfl_down_sync(0xffffffffu, hn, 8);
        float v2 = __shfl_down_sync(0xffffffffu, hn, 16);
        float v3 = __shfl_down_sync(0xffffffffu, hn, 24);
        if (storer) {
            uint32_t boff = (uint32_t)(nxt * HBYTES);
#pragma unroll
            for (int pr = 0; pr < CLUSTER; pr++) {
                st_clu64(rbase[pr] + boff,     hn, v1);
                st_clu64(rbase[pr] + boff + 8, v2, v3);
            }
        }
        carrive();

        // Delayed attention on h_t = buf[cur] (skip t=0: h_0 = 0 state).
        // Runs inside the arrive->wait window; buf[cur] is not overwritten by
        // peers until step t+2 (triple buffering makes this safe).
        if (t > 0 && tid < 64) {
            int w = tid >> 5, l = tid & 31;
            const float* hr = S.hb[cur][w];
            float p = 0.f;
#pragma unroll
            for (int j = l; j < 256; j += 32) p += hr[j] * S.wa[j];
#pragma unroll
            for (int ofs = 16; ofs > 0; ofs >>= 1) p += __shfl_xor_sync(0xffffffffu, p, ofs);
            float mn  = fmaxf(m_run, p);
            float sc  = expf(m_run - mn);
            float wgt = expf(p - mn);
            Z_run = Z_run * sc + wgt;
            m_run = mn;
            C0 = C0 * sc + wgt * hr[U0 + l];
            C1 = C1 * sc + wgt * hr[U0 + 32 + l];
        }
        cwait();
        cur = nxt;
    }
    // h_1024 lives in buf[cur] (cur == 1024 % 3 == 1)

    // Tail: accumulate the last state h_1024 into the softmax
    if (tid < 64) {
        int w = tid >> 5, l = tid & 31;
        const float* hr = S.hb[cur][w];
        float p = 0.f;
#pragma unroll
        for (int j = l; j < 256; j += 32) p += hr[j] * S.wa[j];
#pragma unroll
        for (int ofs = 16; ofs > 0; ofs >>= 1) p += __shfl_xor_sync(0xffffffffu, p, ofs);
        float mn  = fmaxf(m_run, p);
        float sc  = expf(m_run - mn);
        float wgt = expf(p - mn);
        Z_run = Z_run * sc + wgt;
        m_run = mn;
        C0 = C0 * sc + wgt * hr[U0 + l];
        C1 = C1 * sc + wgt * hr[U0 + 32 + l];
    }

    // ---------------- Phase 1.5: context c -> buf[2]; s0 -> buf[0] ----------------
    __syncthreads();
    if (tid < 64) {
        int w = tid >> 5, l = tid & 31;
        float iz = 1.f / Z_run;
        S.red[w * 64 + l]      = C0 * iz;
        S.red[w * 64 + 32 + l] = C1 * iz;
    }
    // copy s0 = h_1024 (buf[cur]) into buf[0] locally (every CTA holds full h)
    for (int idx = tid; idx < B_TILE * HB_PAD; idx += NTHREADS)
        ((float*)S.hb[0])[idx] = ((const float*)S.hb[cur])[idx];
    __syncthreads();
    if (storer) {
        float c0 = S.red[pb * 64 + u],     c1 = S.red[pb * 64 + u + 1];
        float c2 = S.red[pb * 64 + u + 2], c3 = S.red[pb * 64 + u + 3];
        uint32_t boff = (uint32_t)(2 * HBYTES);
#pragma unroll
        for (int pr = 0; pr < CLUSTER; pr++) {
            st_clu64(rbase[pr] + boff,     c0, c1);
            st_clu64(rbase[pr] + boff + 8, c2, c3);
        }
    }
    csync();

    // decoder input weights; giD = W_ih_d . c + b_ih_d (registers, primary batch)
    for (int idx = tid; idx < ROWSL * Hdim; idx += NTHREADS) {
        int lr = idx >> 8, k = idx & 255;
        int grow = (lr >> 6) * Hdim + U0 + (lr & 63);
        S.Wh[lr * WH_PAD + k] = Wihd[grow * Hdim + k];
    }
    __syncthreads();
    float gid0, gid1, gid2;
    {
        float s0, s1, s2;
        dot3b(wp0, wp1, wp2,
              &S.hb[2][0][hoff], &S.hb[2][1][hoff], o, s0, s1, s2);
        gid0 = bihd[U0 + u] + s0;
        gid1 = bihd[Hdim + U0 + u] + s1;
        gid2 = bihd[2 * Hdim + U0 + u] + s2;
    }
    __syncthreads();

    // decoder recurrent weights + biases
    for (int idx = tid; idx < ROWSL * Hdim; idx += NTHREADS) {
        int lr = idx >> 8, k = idx & 255;
        int grow = (lr >> 6) * Hdim + U0 + (lr & 63);
        S.Wh[lr * WH_PAD + k] = Whhd[grow * Hdim + k];
    }
    bg0 = bhhd[U0 + u];
    bg1 = bhhd[Hdim + U0 + u];
    bg2 = bhhd[2 * Hdim + U0 + u];
    const float bdec = bdec_p[0];
    __syncthreads();
    csync();

    // ---------------- Phase 2: decoder GRU (constant input gates, delayed y) ----
    cur = 0;
    for (int i = 0; i < Lseq; i++) {
        int nxt = cur + 1; if (nxt == NBUF) nxt = 0;

        float s0, s1, s2;
        dot3b(wp0, wp1, wp2,
              &S.hb[cur][0][hoff], &S.hb[cur][1][hoff], o, s0, s1, s2);

        float r  = sigf(gid0 + bg0 + s0);
        float z  = sigf(gid1 + bg1 + s1);
        float nn = tanhf(gid2 + r * (bg2 + s2));
        float sn = nn + z * (hprev - nn);
        hprev = sn;

        float v1 = __shfl_down_sync(0xffffffffu, sn, 8);
        float v2 = __shfl_down_sync(0xffffffffu, sn, 16);
        float v3 = __shfl_down_sync(0xffffffffu, sn, 24);
        if (storer) {
            uint32_t boff = (uint32_t)(nxt * HBYTES);
#pragma unroll
            for (int pr = 0; pr < CLUSTER; pr++) {
                st_clu64(rbase[pr] + boff,     sn, v1);
                st_clu64(rbase[pr] + boff + 8, v2, v3);
            }
        }
        carrive();

        // Delayed y: y_{i-1} = sigmoid(s_i . w_dec + b_dec), s_i = buf[cur]
        if (i > 0 && tid < 64) {
            int w = tid >> 5, l = tid & 31;
            const float* hr = S.hb[cur][w];
            float p = 0.f;
#pragma unroll
            for (int j = l; j < 256; j += 32) p += hr[j] * S.wdec[j];
#pragma unroll
            for (int ofs = 16; ofs > 0; ofs >>= 1) p += __shfl_xor_sync(0xffffffffu, p, ofs);
            if (l == 0) S.yb[(i - 1) * 2 + w] = sigf(p + bdec);
        }
        cwait();
        cur = nxt;
    }
    // Tail: y_1023 from s_1024 = buf[cur]
    if (tid < 64) {
        int w = tid >> 5, l = tid & 31;
        const float* hr = S.hb[cur][w];
        float p = 0.f;
#pragma unroll
        for (int j = l; j < 256; j += 32) p += hr[j] * S.wdec[j];
#pragma unroll
        for (int ofs = 16; ofs > 0; ofs >>= 1) p += __shfl_xor_sync(0xffffffffu, p, ofs);
        if (l == 0) S.yb[(Lseq - 1) * 2 + w] = sigf(p + bdec);
    }

    // ---------------- Phase 3: out = y @ W_out^T + b_out ----------------
    __syncthreads();
    {
        int part = tid >> 6;                // 0..7
        int ob   = tid & 63;                // 32 o-rows x 2 batches
        int orow = (int)rank * 32 + (ob >> 1);
        int b    = ob & 1;
        float acc = 0.f;
        for (int i = part; i < Lseq; i += PARTS)
            acc += S.yb[i * 2 + b] * Wout[orow * Lseq + i];
        S.red[ob * PARTS + part] = acc;
    }
    __syncthreads();
    if (tid < 64) {
        int orow = (int)rank * 32 + (tid >> 1);
        int b    = tid & 1;
        float s  = bout[orow];
#pragma unroll
        for (int p8 = 0; p8 < PARTS; p8++) s += S.red[tid * PARTS + p8];
        out[(b0 + b) * OUTD + orow] = s;
    }
}

extern "C" void kernel_launch(void* const* d_in, const int* in_sizes, int n_in,
                              void* d_out, int out_size) {
    (void)in_sizes; (void)n_in; (void)out_size;

    // Pre-kernel: gi = x @ W_ih_e^T + b_ih_e for all timesteps
    gi_kernel<<<dim3(Lseq, 3), 256>>>(
        (const float*)d_in[0], (const float*)d_in[1], (const float*)d_in[3]);

    cudaFuncSetAttribute(attn_net_kernel,
                         cudaFuncAttributeMaxDynamicSharedMemorySize,
                         (int)sizeof(Smem));
    attn_net_kernel<<<128, NTHREADS, sizeof(Smem)>>>(
        (const float*)d_in[0],  (const float*)d_in[1],  (const float*)d_in[2],
        (const float*)d_in[3],  (const float*)d_in[4],  (const float*)d_in[5],
        (const float*)d_in[6],  (const float*)d_in[7],  (const float*)d_in[8],
        (const float*)d_in[9],  (const float*)d_in[10], (const float*)d_in[11],
        (const float*)d_in[12], (const float*)d_in[13], (const float*)d_in[14],
        (float*)d_out);
}